// round 4
// baseline (speedup 1.0000x reference)
#include <cuda_runtime.h>
#include <math.h>
#include <stdint.h>

#define T_LEN 64
#define BATCH 32
#define SEQ   400
#define HID   512
#define VOC   50000
#define EXTD  400
#define VE    (VOC+EXTD)
#define TB    (T_LEN*BATCH)     /* 2048 */
#define H3    (3*HID)           /* 1536 */

/* ---------------- scratch (device globals: allocation-free) -------------- */
__device__ float g_cat [TB*H3];             /* (T*B, 3H) rows t*B+b          */
__device__ float g_qB  [BATCH*T_LEN*HID];   /* (B,T,H)                       */
__device__ float g_kB  [BATCH*SEQ*HID];     /* (B,S,H)                       */
__device__ float g_valT[BATCH*HID*SEQ];     /* (B,H,S)                       */
__device__ float g_w   [BATCH*T_LEN*SEQ];   /* (B,T,S) attn weights          */
__device__ float g_atts[TB*HID];            /* (B,T,H) rows b*T+t            */

/* ---------------- generic TF32 MMA GEMM: C = alpha*(A@B^T + bias) -------- */
struct GP {
  const float* A; const float* B; const float* B2;
  float* C; float* C2;
  long lda, ldb, ldc;
  long sA, sB, sC;            /* batch strides (grid.z)                      */
  int  M, N, K;
  const float* bias; const float* bias2;
  float alpha;
  int  mode, D1, D2;          /* epilogue index modes                        */
  long col_off;
};

#define BN 128
#define BK 32

__device__ __forceinline__ void cpa16u(unsigned dst, const float* src, int bytes){
  asm volatile("cp.async.cg.shared.global [%0], [%1], 16, %2;\n"
               :: "r"(dst), "l"(src), "r"(bytes));
}
#define CPA_COMMIT() asm volatile("cp.async.commit_group;\n")
#define CPA_WAIT1()  asm volatile("cp.async.wait_group 1;\n")

#define LDSM_X4(r0,r1,r2,r3,addr) \
  asm volatile("ldmatrix.sync.aligned.m8n8.x4.shared.b16 {%0,%1,%2,%3}, [%4];" \
               : "=r"(r0), "=r"(r1), "=r"(r2), "=r"(r3) : "r"(addr))

#define MMA8(d, a0,a1,a2,a3, b0,b1) \
  asm volatile("mma.sync.aligned.m16n8k8.row.col.f32.tf32.tf32.f32 " \
               "{%0,%1,%2,%3}, {%4,%5,%6,%7}, {%8,%9}, {%0,%1,%2,%3};\n" \
               : "+f"((d)[0]), "+f"((d)[1]), "+f"((d)[2]), "+f"((d)[3]) \
               : "r"(a0), "r"(a1), "r"(a2), "r"(a3), "r"(b0), "r"(b1))

__device__ __forceinline__ void epi(const GP& p, float* C, int m, int n, float v){
  if (m >= p.M || n >= p.N) return;
  if (p.mode == 3){                    /* fused k/val projection epilogue    */
    int s = m / BATCH, b = m % BATCH;
    if (n < HID){                      /* k -> (B,S,H) */
      p.C[((long)b*SEQ + s)*HID + n] = v + p.bias[n];
    } else {                           /* val -> (B,H,S) */
      int nn = n - HID;
      p.C2[((long)b*HID + nn)*SEQ + s] = v + p.bias2[nn];
    }
    return;
  }
  float bb = p.bias ? p.bias[n] : 0.f;
  float o = p.alpha * (v + bb);
  long idx;
  if (p.mode == 0)      idx = (long)m * p.ldc + p.col_off + n;
  else                  idx = (long)((m % p.D1) * p.D2 + m / p.D1) * p.ldc + p.col_off + n;
  C[idx] = o;
}

template<int BMT, int DUAL>
__global__ __launch_bounds__(256) void gemm_tf32(GP p){
  constexpr int WM   = BMT/32;         /* warp rows: 4 or 2                  */
  constexpr int NCOL = BN/(8/WM);      /* warp cols: 64 or 32                */
  constexpr int NFR  = NCOL/8;         /* n frags:   8 or 4                  */
  constexpr int NBL  = NCOL/16;        /* B ldsm.x4: 4 or 2                  */
  constexpr int ABYT = BMT*BK*4;
  constexpr int SBYT = ABYT + BN*BK*4;
  constexpr int GT   = (BMT+BN)*8;     /* 16B granules per stage             */

  extern __shared__ float smf[];
  uint32_t sbase = (uint32_t)__cvta_generic_to_shared(smf);
  const float* A  = p.A + (long)blockIdx.z * p.sA;
  const float* Bg = p.B + (long)blockIdx.z * p.sB;
  float*       C  = p.C + (long)blockIdx.z * p.sC;

  int tid = threadIdx.x;
  int lane = tid & 31, warp = tid >> 5;
  int wm = warp % WM, wn = warp / WM;
  int m0 = blockIdx.x * BMT, n0 = blockIdx.y * BN;

  float acc[2][NFR][4];
  #pragma unroll
  for (int i=0;i<2;i++)
    #pragma unroll
    for (int j=0;j<NFR;j++){ acc[i][j][0]=0.f; acc[i][j][1]=0.f; acc[i][j][2]=0.f; acc[i][j][3]=0.f; }

  int ktiles = (p.K + BK - 1)/BK;

  auto load = [&](int st, int k0){
    uint32_t ab = sbase + st*SBYT;
    uint32_t bb = ab + ABYT;
    #pragma unroll
    for (int i=0;i<GT/256;i++){
      int g = tid + i*256;
      int r = g >> 3, gc = g & 7;
      int kcol = k0 + gc*4;
      int kleft = p.K - kcol;
      int kb = (kleft >= 4) ? 16 : (kleft > 0 ? kleft*4 : 0);
      if (r < BMT){
        uint32_t soff = (uint32_t)(r*128 + ((gc ^ (r&7))<<4));
        int gm = m0 + r;
        cpa16u(ab + soff, A + (long)gm*p.lda + kcol, (gm < p.M) ? kb : 0);
      } else {
        int rb = r - BMT;
        uint32_t soff = (uint32_t)(rb*128 + ((gc ^ (rb&7))<<4));
        int gn = n0 + rb;
        const float* src;
        if (DUAL && gn >= HID) src = p.B2 + (long)(gn-HID)*p.ldb + kcol;
        else                   src = Bg  + (long)gn*p.ldb + kcol;
        cpa16u(bb + soff, src, (gn < p.N) ? kb : 0);
      }
    }
  };

  load(0, 0); CPA_COMMIT();
  load(1, BK); CPA_COMMIT();

  int mi1 = (lane >> 3) & 1;
  int kg2 = lane >> 4;
  int ri  = lane & 7;
  int marow = wm*32 + mi1*8 + ri;
  int nbrow = wn*NCOL + mi1*8 + ri;
  int maxor = (marow & 7);
  int nbxor = (nbrow & 7);

  for (int kt = 0; kt < ktiles; kt++){
    CPA_WAIT1();
    __syncthreads();
    if (kt + 2 < ktiles) load((kt+2)%3, (kt+2)*BK);
    CPA_COMMIT();

    uint32_t ab = sbase + (kt%3)*SBYT;
    uint32_t aA = ab + marow*128;
    uint32_t aB = ab + ABYT + nbrow*128;

    #pragma unroll
    for (int kk=0; kk<4; kk++){
      uint32_t asw = (uint32_t)(((kk*2 + kg2) ^ maxor) << 4);
      uint32_t bsw = (uint32_t)(((kk*2 + kg2) ^ nbxor) << 4);
      unsigned af0[4], af1[4], bf[NBL][4];
      LDSM_X4(af0[0],af0[1],af0[2],af0[3], aA + asw);
      LDSM_X4(af1[0],af1[1],af1[2],af1[3], aA + asw + 16*128);
      #pragma unroll
      for (int jp=0; jp<NBL; jp++)
        LDSM_X4(bf[jp][0],bf[jp][1],bf[jp][2],bf[jp][3], aB + bsw + jp*16*128);
      #pragma unroll
      for (int jp=0; jp<NBL; jp++){
        MMA8(acc[0][2*jp  ], af0[0],af0[1],af0[2],af0[3], bf[jp][0], bf[jp][2]);
        MMA8(acc[0][2*jp+1], af0[0],af0[1],af0[2],af0[3], bf[jp][1], bf[jp][3]);
        MMA8(acc[1][2*jp  ], af1[0],af1[1],af1[2],af1[3], bf[jp][0], bf[jp][2]);
        MMA8(acc[1][2*jp+1], af1[0],af1[1],af1[2],af1[3], bf[jp][1], bf[jp][3]);
      }
    }
  }

  int r = lane >> 2, c2 = (lane & 3)*2;
  #pragma unroll
  for (int im=0; im<2; im++)
    #pragma unroll
    for (int jn=0; jn<NFR; jn++){
      int mr = m0 + wm*32 + im*16 + r;
      int nc = n0 + wn*NCOL + jn*8 + c2;
      epi(p, C, mr,   nc,   acc[im][jn][0]);
      epi(p, C, mr,   nc+1, acc[im][jn][1]);
      epi(p, C, mr+8, nc,   acc[im][jn][2]);
      epi(p, C, mr+8, nc+1, acc[im][jn][3]);
    }
}

/* ---------------- cat[:, 0:1024] = [h, y_emb] ---------------------------- */
__global__ void cat_copy(const float* __restrict__ h, const float* __restrict__ y){
  int i = blockIdx.x*blockDim.x + threadIdx.x;
  if (i >= TB*(HID/4)) return;
  int row = i / (HID/4);
  int c   = i % (HID/4);
  const float4* h4 = (const float4*)h;
  const float4* y4 = (const float4*)y;
  float4* cat4 = (float4*)g_cat;
  cat4[(long)row*(H3/4) + c]           = h4[i];
  cat4[(long)row*(H3/4) + (HID/4) + c] = y4[i];
}

/* ---------------- softmax over S; writes w (B,T,S) + dists (T,B,S) ------- */
__global__ void softmax_s(float* __restrict__ dists, const unsigned char* __restrict__ mask){
  int bt = blockIdx.x;                  /* b*T + t */
  int b = bt / T_LEN, t = bt % T_LEN;
  float* row = g_w + (long)bt*SEQ;
  const unsigned char* mrow = mask + (long)b*SEQ;
  int tid = threadIdx.x;                /* 128 */
  __shared__ float red[128];
  float mx = -1e30f;
  for (int s=tid; s<SEQ; s+=128){
    float x = mrow[s] ? -1e9f : row[s];
    mx = fmaxf(mx, x);
  }
  red[tid]=mx; __syncthreads();
  for (int off=64; off>0; off>>=1){ if (tid<off) red[tid]=fmaxf(red[tid],red[tid+off]); __syncthreads(); }
  mx = red[0]; __syncthreads();
  float sum=0.f;
  for (int s=tid; s<SEQ; s+=128){
    float x = mrow[s] ? -1e9f : row[s];
    sum += __expf(x-mx);
  }
  red[tid]=sum; __syncthreads();
  for (int off=64; off>0; off>>=1){ if (tid<off) red[tid]+=red[tid+off]; __syncthreads(); }
  float inv = 1.f/red[0];
  for (int s=tid; s<SEQ; s+=128){
    float x = mrow[s] ? -1e9f : row[s];
    float wv = __expf(x-mx)*inv;
    row[s] = wv;
    dists[((long)t*BATCH + b)*SEQ + s] = wv;
  }
}

/* -------- fused: gate + softmax over V + ext zero + pointer scatter ------ */
__global__ void softmax_v(float* __restrict__ out, const int* __restrict__ xids,
                          const float* __restrict__ vv, const float* __restrict__ bvv){
  int rid = blockIdx.x;                 /* t*B + b */
  int b = rid % BATCH, t = rid / BATCH;
  float* row = out + (long)rid*VE;
  int tid = threadIdx.x;                /* 512 */
  __shared__ float rm[512], rs[512];
  __shared__ float gsh;

  /* gate = sigmoid(cat[rid] . v + bv) */
  const float* cr = g_cat + (long)rid*H3;
  float s0 = 0.f;
  for (int j=tid; j<H3; j+=512) s0 += cr[j]*vv[j];
  rm[tid]=s0; __syncthreads();
  for (int off=256; off>0; off>>=1){ if (tid<off) rm[tid]+=rm[tid+off]; __syncthreads(); }
  if (tid==0) gsh = 1.f/(1.f+__expf(-(rm[0]+bvv[0])));
  __syncthreads();
  float g = gsh;

  /* online softmax over V */
  float m = row[tid], s = 1.f;
  for (int j=tid+512; j<VOC; j+=512){
    float x = row[j];
    if (x > m){ s = s*__expf(m-x) + 1.f; m = x; }
    else        s += __expf(x-m);
  }
  rm[tid]=m; rs[tid]=s; __syncthreads();
  for (int off=256; off>0; off>>=1){
    if (tid<off){
      float m2=rm[tid+off], s2=rs[tid+off];
      float M=fmaxf(rm[tid],m2);
      rs[tid]=rs[tid]*__expf(rm[tid]-M)+s2*__expf(m2-M);
      rm[tid]=M;
    }
    __syncthreads();
  }
  float M = rm[0];
  float gscale = g/rs[0];
  for (int j=tid; j<VOC; j+=512) row[j] = __expf(row[j]-M)*gscale;
  for (int j=VOC+tid; j<VE; j+=512) row[j] = 0.f;

  /* order the stores before cross-thread atomics on the same row */
  __threadfence(); __syncthreads();

  float omg = 1.f - g;
  for (int si=tid; si<SEQ; si+=512){
    float wv = g_w[((long)b*T_LEN + t)*SEQ + si];
    int col = xids[(long)si*BATCH + b];
    atomicAdd(row + col, omg*wv);
  }
}

/* ------------------------------- host ----------------------------------- */
template<int BMT, int DUAL>
static inline void launch_gemm(const GP& p, int batches){
  constexpr int SM = 3*((BMT+BN)*BK*4);
  static bool done = false;
  if (!done){
    cudaFuncSetAttribute(gemm_tf32<BMT,DUAL>,
                         cudaFuncAttributeMaxDynamicSharedMemorySize, SM);
    done = true;
  }
  dim3 grid((p.M+BMT-1)/BMT, (p.N+BN-1)/BN, batches);
  gemm_tf32<BMT,DUAL><<<grid, 256, SM>>>(p);
}

extern "C" void kernel_launch(void* const* d_in, const int* in_sizes, int n_in,
                              void* d_out, int out_size){
  const float* h    = (const float*)d_in[0];
  const float* yemb = (const float*)d_in[1];
  const float* mem  = (const float*)d_in[2];
  const unsigned char* mask = (const unsigned char*)d_in[3];
  const int* xids   = (const int*)d_in[4];
  int wb = 5;
  if (n_in >= 18 && in_sizes[5] == 1) wb = 6;   /* max_ext_len scalar present */
  const float* Wq = (const float*)d_in[wb+0];
  const float* bq = (const float*)d_in[wb+1];
  const float* Wk = (const float*)d_in[wb+2];
  const float* bk = (const float*)d_in[wb+3];
  const float* Wv = (const float*)d_in[wb+4];
  const float* bva= (const float*)d_in[wb+5];
  const float* Wo = (const float*)d_in[wb+6];
  const float* bo = (const float*)d_in[wb+7];
  const float* Wp = (const float*)d_in[wb+8];
  const float* bp = (const float*)d_in[wb+9];
  const float* vv = (const float*)d_in[wb+10];
  const float* bv = (const float*)d_in[wb+11];

  float* out   = (float*)d_out;
  float* dists = out + (long)TB*VE;

  void *qB, *kB, *valT, *wbuf, *attsB, *catp;
  cudaGetSymbolAddress(&qB,   g_qB);
  cudaGetSymbolAddress(&kB,   g_kB);
  cudaGetSymbolAddress(&valT, g_valT);
  cudaGetSymbolAddress(&wbuf, g_w);
  cudaGetSymbolAddress(&attsB,g_atts);
  cudaGetSymbolAddress(&catp, g_cat);

  float scale = 1.0f/sqrtf((float)HID);

  /* cat[:,0:1024] = [h, y_emb] */
  cat_copy<<<(TB*(HID/4)+255)/256, 256>>>(h, yemb);

  GP p;

  /* q = (h@Wq^T + bq)*scale -> (B,T,H) */
  p = GP{};
  p.A = h; p.B = Wq; p.C = (float*)qB;
  p.lda = HID; p.ldb = HID; p.ldc = HID;
  p.M = TB; p.N = HID; p.K = HID;
  p.bias = bq; p.alpha = scale;
  p.mode = 1; p.D1 = BATCH; p.D2 = T_LEN;
  launch_gemm<64,0>(p, 1);

  /* fused k & val projection: B rows [0,512)=Wk, [512,1024)=Wv */
  p = GP{};
  p.A = mem; p.B = Wk; p.B2 = Wv;
  p.C = (float*)kB; p.C2 = (float*)valT;
  p.lda = HID; p.ldb = HID;
  p.M = SEQ*BATCH; p.N = 2*HID; p.K = HID;
  p.bias = bk; p.bias2 = bva; p.alpha = 1.f;
  p.mode = 3;
  launch_gemm<128,1>(p, 1);

  /* scores[b]: (T,S) = q_b @ k_b^T */
  p = GP{};
  p.A = (const float*)qB; p.B = (const float*)kB; p.C = (float*)wbuf;
  p.lda = HID; p.ldb = HID; p.ldc = SEQ;
  p.sA = (long)T_LEN*HID; p.sB = (long)SEQ*HID; p.sC = (long)T_LEN*SEQ;
  p.M = T_LEN; p.N = SEQ; p.K = HID;
  p.alpha = 1.f; p.mode = 0;
  launch_gemm<64,0>(p, BATCH);

  softmax_s<<<BATCH*T_LEN, 128>>>(dists, mask);

  /* atts[b]: (T,H) = w_b @ valT_b^T */
  p = GP{};
  p.A = (const float*)wbuf; p.B = (const float*)valT; p.C = (float*)attsB;
  p.lda = SEQ; p.ldb = SEQ; p.ldc = HID;
  p.sA = (long)T_LEN*SEQ; p.sB = (long)HID*SEQ; p.sC = (long)T_LEN*HID;
  p.M = T_LEN; p.N = HID; p.K = SEQ;
  p.alpha = 1.f; p.mode = 0;
  launch_gemm<64,0>(p, BATCH);

  /* cat[:,1024:1536] = atts@Wo^T + bo  (rows b*T+t -> t*B+b) */
  p = GP{};
  p.A = (const float*)attsB; p.B = Wo; p.C = (float*)catp;
  p.lda = HID; p.ldb = HID; p.ldc = H3;
  p.M = TB; p.N = HID; p.K = HID;
  p.bias = bo; p.alpha = 1.f;
  p.mode = 1; p.D1 = T_LEN; p.D2 = BATCH; p.col_off = 1024;
  launch_gemm<64,0>(p, 1);

  /* logits = cat@Wp^T + bp -> d_out rows, ldc = V+EXT */
  p = GP{};
  p.A = (const float*)catp; p.B = Wp; p.C = out;
  p.lda = H3; p.ldb = H3; p.ldc = VE;
  p.M = TB; p.N = VOC; p.K = H3;
  p.bias = bp; p.alpha = 1.f; p.mode = 0;
  launch_gemm<128,0>(p, 1);

  /* fused gate + softmax over V + ext zero + scatter */
  softmax_v<<<TB, 512>>>(out, xids, vv, bv);

  (void)out_size; (void)n_in;
}

// round 5
// speedup vs baseline: 1.4856x; 1.4856x over previous
#include <cuda_runtime.h>
#include <math.h>
#include <stdint.h>

#define T_LEN 64
#define BATCH 32
#define SEQ   400
#define HID   512
#define VOC   50000
#define EXTD  400
#define VE    (VOC+EXTD)
#define TB    (T_LEN*BATCH)     /* 2048 */
#define H3    (3*HID)           /* 1536 */

/* ---------------- scratch (device globals: allocation-free) -------------- */
__device__ float g_cat [TB*H3];             /* (T*B, 3H) rows t*B+b          */
__device__ float g_qB  [BATCH*T_LEN*HID];   /* (B,T,H)                       */
__device__ float g_kB  [BATCH*SEQ*HID];     /* (B,S,H)                       */
__device__ float g_valT[BATCH*HID*SEQ];     /* (B,H,S)                       */
__device__ float g_w   [BATCH*T_LEN*SEQ];   /* (B,T,S) attn weights          */
__device__ float g_atts[TB*HID];            /* (B,T,H) rows b*T+t            */

/* ---------------- generic TF32 MMA GEMM: C = alpha*(A@B^T + bias) -------- */
struct GP {
  const float* A; const float* B; const float* B2;
  float* C; float* C2;
  long lda, ldb, ldc;
  long sA, sB, sC;            /* batch strides (grid.z)                      */
  int  M, N, K;
  const float* bias; const float* bias2;
  float alpha;
  int  mode, D1, D2;          /* epilogue index modes                        */
  long col_off;
};

#define BN 128
#define BK 32

__device__ __forceinline__ void cpa16u(unsigned dst, const float* src, int bytes){
  asm volatile("cp.async.cg.shared.global [%0], [%1], 16, %2;\n"
               :: "r"(dst), "l"(src), "r"(bytes));
}
#define CPA_COMMIT() asm volatile("cp.async.commit_group;\n")
#define CPA_WAIT2()  asm volatile("cp.async.wait_group 2;\n")

#define LDSM_X4(r0,r1,r2,r3,addr) \
  asm volatile("ldmatrix.sync.aligned.m8n8.x4.shared.b16 {%0,%1,%2,%3}, [%4];" \
               : "=r"(r0), "=r"(r1), "=r"(r2), "=r"(r3) : "r"(addr))

#define MMA8(d, a0,a1,a2,a3, b0,b1) \
  asm volatile("mma.sync.aligned.m16n8k8.row.col.f32.tf32.tf32.f32 " \
               "{%0,%1,%2,%3}, {%4,%5,%6,%7}, {%8,%9}, {%0,%1,%2,%3};\n" \
               : "+f"((d)[0]), "+f"((d)[1]), "+f"((d)[2]), "+f"((d)[3]) \
               : "r"(a0), "r"(a1), "r"(a2), "r"(a3), "r"(b0), "r"(b1))

__device__ __forceinline__ void epi(const GP& p, float* C, int m, int n, float v){
  if (m >= p.M || n >= p.N) return;
  if (p.mode == 3){                    /* fused k/val projection epilogue    */
    int s = m / BATCH, b = m % BATCH;
    if (n < HID){                      /* k -> (B,S,H) */
      p.C[((long)b*SEQ + s)*HID + n] = v + p.bias[n];
    } else {                           /* val -> (B,H,S) */
      int nn = n - HID;
      p.C2[((long)b*HID + nn)*SEQ + s] = v + p.bias2[nn];
    }
    return;
  }
  float bb = p.bias ? p.bias[n] : 0.f;
  float o = p.alpha * (v + bb);
  long idx;
  if (p.mode == 0)      idx = (long)m * p.ldc + p.col_off + n;
  else                  idx = (long)((m % p.D1) * p.D2 + m / p.D1) * p.ldc + p.col_off + n;
  C[idx] = o;
}

template<int BMT, int DUAL>
__global__ __launch_bounds__(256) void gemm_tf32(GP p){
  constexpr int WM   = BMT/32;         /* warp rows: 4 or 2                  */
  constexpr int NCOL = BN/(8/WM);      /* warp cols: 64 or 32                */
  constexpr int NFR  = NCOL/8;         /* n frags:   8 or 4                  */
  constexpr int NBL  = NCOL/16;        /* B ldsm.x4: 4 or 2                  */
  constexpr int ABYT = BMT*BK*4;
  constexpr int SBYT = ABYT + BN*BK*4;
  constexpr int GT   = (BMT+BN)*8;     /* 16B granules per stage             */

  extern __shared__ float smf[];
  uint32_t sbase = (uint32_t)__cvta_generic_to_shared(smf);
  const float* A  = p.A + (long)blockIdx.z * p.sA;
  const float* Bg = p.B + (long)blockIdx.z * p.sB;
  float*       C  = p.C + (long)blockIdx.z * p.sC;

  int tid = threadIdx.x;
  int lane = tid & 31, warp = tid >> 5;
  int wm = warp % WM, wn = warp / WM;
  int m0 = blockIdx.x * BMT, n0 = blockIdx.y * BN;

  float acc[2][NFR][4];
  #pragma unroll
  for (int i=0;i<2;i++)
    #pragma unroll
    for (int j=0;j<NFR;j++){ acc[i][j][0]=0.f; acc[i][j][1]=0.f; acc[i][j][2]=0.f; acc[i][j][3]=0.f; }

  int ktiles = (p.K + BK - 1)/BK;

  auto load = [&](int st, int k0){
    uint32_t ab = sbase + st*SBYT;
    uint32_t bb = ab + ABYT;
    #pragma unroll
    for (int i=0;i<GT/256;i++){
      int g = tid + i*256;
      int r = g >> 3, gc = g & 7;
      int kcol = k0 + gc*4;
      int kleft = p.K - kcol;
      int kb = (kleft >= 4) ? 16 : (kleft > 0 ? kleft*4 : 0);
      if (r < BMT){
        uint32_t soff = (uint32_t)(r*128 + ((gc ^ (r&7))<<4));
        int gm = m0 + r;
        cpa16u(ab + soff, A + (long)gm*p.lda + kcol, (gm < p.M) ? kb : 0);
      } else {
        int rb = r - BMT;
        uint32_t soff = (uint32_t)(rb*128 + ((gc ^ (rb&7))<<4));
        int gn = n0 + rb;
        const float* src;
        if (DUAL && gn >= HID) src = p.B2 + (long)(gn-HID)*p.ldb + kcol;
        else                   src = Bg  + (long)gn*p.ldb + kcol;
        cpa16u(bb + soff, src, (gn < p.N) ? kb : 0);
      }
    }
  };

  load(0, 0); CPA_COMMIT();
  load(1, BK); CPA_COMMIT();

  int mi1 = (lane >> 3) & 1;
  int kg2 = lane >> 4;
  int ri  = lane & 7;
  int marow = wm*32 + mi1*8 + ri;
  int nbrow = wn*NCOL + mi1*8 + ri;
  int maxor = (marow & 7);
  int nbxor = (nbrow & 7);

  /* R3-proven pipeline: issue -> commit -> wait2 -> sync -> compute -> sync */
  for (int kt = 0; kt < ktiles; kt++){
    if (kt + 2 < ktiles) load((kt+2)%3, (kt+2)*BK);
    CPA_COMMIT();
    CPA_WAIT2();
    __syncthreads();

    uint32_t ab = sbase + (kt%3)*SBYT;
    uint32_t aA = ab + marow*128;
    uint32_t aB = ab + ABYT + nbrow*128;

    #pragma unroll
    for (int kk=0; kk<4; kk++){
      uint32_t asw = (uint32_t)(((kk*2 + kg2) ^ maxor) << 4);
      uint32_t bsw = (uint32_t)(((kk*2 + kg2) ^ nbxor) << 4);
      unsigned af0[4], af1[4], bf[NBL][4];
      LDSM_X4(af0[0],af0[1],af0[2],af0[3], aA + asw);
      LDSM_X4(af1[0],af1[1],af1[2],af1[3], aA + asw + 16*128);
      #pragma unroll
      for (int jp=0; jp<NBL; jp++)
        LDSM_X4(bf[jp][0],bf[jp][1],bf[jp][2],bf[jp][3], aB + bsw + jp*16*128);
      #pragma unroll
      for (int jp=0; jp<NBL; jp++){
        MMA8(acc[0][2*jp  ], af0[0],af0[1],af0[2],af0[3], bf[jp][0], bf[jp][2]);
        MMA8(acc[0][2*jp+1], af0[0],af0[1],af0[2],af0[3], bf[jp][1], bf[jp][3]);
        MMA8(acc[1][2*jp  ], af1[0],af1[1],af1[2],af1[3], bf[jp][0], bf[jp][2]);
        MMA8(acc[1][2*jp+1], af1[0],af1[1],af1[2],af1[3], bf[jp][1], bf[jp][3]);
      }
    }
    __syncthreads();
  }

  int r = lane >> 2, c2 = (lane & 3)*2;
  #pragma unroll
  for (int im=0; im<2; im++)
    #pragma unroll
    for (int jn=0; jn<NFR; jn++){
      int mr = m0 + wm*32 + im*16 + r;
      int nc = n0 + wn*NCOL + jn*8 + c2;
      epi(p, C, mr,   nc,   acc[im][jn][0]);
      epi(p, C, mr,   nc+1, acc[im][jn][1]);
      epi(p, C, mr+8, nc,   acc[im][jn][2]);
      epi(p, C, mr+8, nc+1, acc[im][jn][3]);
    }
}

/* ---------------- cat[:, 0:1024] = [h, y_emb] ---------------------------- */
__global__ void cat_copy(const float* __restrict__ h, const float* __restrict__ y){
  int i = blockIdx.x*blockDim.x + threadIdx.x;
  if (i >= TB*(HID/4)) return;
  int row = i / (HID/4);
  int c   = i % (HID/4);
  const float4* h4 = (const float4*)h;
  const float4* y4 = (const float4*)y;
  float4* cat4 = (float4*)g_cat;
  cat4[(long)row*(H3/4) + c]           = h4[i];
  cat4[(long)row*(H3/4) + (HID/4) + c] = y4[i];
}

/* ---------------- softmax over S; writes w (B,T,S) + dists (T,B,S) ------- */
__global__ void softmax_s(float* __restrict__ dists, const unsigned char* __restrict__ mask){
  int bt = blockIdx.x;                  /* b*T + t */
  int b = bt / T_LEN, t = bt % T_LEN;
  float* row = g_w + (long)bt*SEQ;
  const unsigned char* mrow = mask + (long)b*SEQ;
  int tid = threadIdx.x;                /* 128 */
  __shared__ float red[128];
  float mx = -1e30f;
  for (int s=tid; s<SEQ; s+=128){
    float x = mrow[s] ? -1e9f : row[s];
    mx = fmaxf(mx, x);
  }
  red[tid]=mx; __syncthreads();
  for (int off=64; off>0; off>>=1){ if (tid<off) red[tid]=fmaxf(red[tid],red[tid+off]); __syncthreads(); }
  mx = red[0]; __syncthreads();
  float sum=0.f;
  for (int s=tid; s<SEQ; s+=128){
    float x = mrow[s] ? -1e9f : row[s];
    sum += __expf(x-mx);
  }
  red[tid]=sum; __syncthreads();
  for (int off=64; off>0; off>>=1){ if (tid<off) red[tid]+=red[tid+off]; __syncthreads(); }
  float inv = 1.f/red[0];
  for (int s=tid; s<SEQ; s+=128){
    float x = mrow[s] ? -1e9f : row[s];
    float wv = __expf(x-mx)*inv;
    row[s] = wv;
    dists[((long)t*BATCH + b)*SEQ + s] = wv;
  }
}

/* -------- fused: gate + softmax over V + ext zero + pointer scatter ------ */
__global__ void softmax_v(float* __restrict__ out, const int* __restrict__ xids,
                          const float* __restrict__ vv, const float* __restrict__ bvv){
  int rid = blockIdx.x;                 /* t*B + b */
  int b = rid % BATCH, t = rid / BATCH;
  float* row = out + (long)rid*VE;
  int tid = threadIdx.x;                /* 512 */
  __shared__ float rm[512], rs[512];
  __shared__ float gsh;

  /* gate = sigmoid(cat[rid] . v + bv) */
  const float* cr = g_cat + (long)rid*H3;
  float s0 = 0.f;
  for (int j=tid; j<H3; j+=512) s0 += cr[j]*vv[j];
  rm[tid]=s0; __syncthreads();
  for (int off=256; off>0; off>>=1){ if (tid<off) rm[tid]+=rm[tid+off]; __syncthreads(); }
  if (tid==0) gsh = 1.f/(1.f+__expf(-(rm[0]+bvv[0])));
  __syncthreads();
  float g = gsh;

  /* online softmax over V */
  float m = row[tid], s = 1.f;
  for (int j=tid+512; j<VOC; j+=512){
    float x = row[j];
    if (x > m){ s = s*__expf(m-x) + 1.f; m = x; }
    else        s += __expf(x-m);
  }
  rm[tid]=m; rs[tid]=s; __syncthreads();
  for (int off=256; off>0; off>>=1){
    if (tid<off){
      float m2=rm[tid+off], s2=rs[tid+off];
      float M=fmaxf(rm[tid],m2);
      rs[tid]=rs[tid]*__expf(rm[tid]-M)+s2*__expf(m2-M);
      rm[tid]=M;
    }
    __syncthreads();
  }
  float M = rm[0];
  float gscale = g/rs[0];
  for (int j=tid; j<VOC; j+=512) row[j] = __expf(row[j]-M)*gscale;
  for (int j=VOC+tid; j<VE; j+=512) row[j] = 0.f;

  /* order the stores before cross-thread atomics on the same row */
  __threadfence(); __syncthreads();

  float omg = 1.f - g;
  for (int si=tid; si<SEQ; si+=512){
    float wv = g_w[((long)b*T_LEN + t)*SEQ + si];
    int col = xids[(long)si*BATCH + b];
    atomicAdd(row + col, omg*wv);
  }
}

/* ------------------------------- host ----------------------------------- */
template<int BMT, int DUAL>
static inline void launch_gemm(const GP& p, int batches){
  constexpr int SM = 3*((BMT+BN)*BK*4);
  static bool done = false;
  if (!done){
    cudaFuncSetAttribute(gemm_tf32<BMT,DUAL>,
                         cudaFuncAttributeMaxDynamicSharedMemorySize, SM);
    done = true;
  }
  dim3 grid((p.M+BMT-1)/BMT, (p.N+BN-1)/BN, batches);
  gemm_tf32<BMT,DUAL><<<grid, 256, SM>>>(p);
}

extern "C" void kernel_launch(void* const* d_in, const int* in_sizes, int n_in,
                              void* d_out, int out_size){
  const float* h    = (const float*)d_in[0];
  const float* yemb = (const float*)d_in[1];
  const float* mem  = (const float*)d_in[2];
  const unsigned char* mask = (const unsigned char*)d_in[3];
  const int* xids   = (const int*)d_in[4];
  int wb = 5;
  if (n_in >= 18 && in_sizes[5] == 1) wb = 6;   /* max_ext_len scalar present */
  const float* Wq = (const float*)d_in[wb+0];
  const float* bq = (const float*)d_in[wb+1];
  const float* Wk = (const float*)d_in[wb+2];
  const float* bk = (const float*)d_in[wb+3];
  const float* Wv = (const float*)d_in[wb+4];
  const float* bva= (const float*)d_in[wb+5];
  const float* Wo = (const float*)d_in[wb+6];
  const float* bo = (const float*)d_in[wb+7];
  const float* Wp = (const float*)d_in[wb+8];
  const float* bp = (const float*)d_in[wb+9];
  const float* vv = (const float*)d_in[wb+10];
  const float* bv = (const float*)d_in[wb+11];

  float* out   = (float*)d_out;
  float* dists = out + (long)TB*VE;

  void *qB, *kB, *valT, *wbuf, *attsB, *catp;
  cudaGetSymbolAddress(&qB,   g_qB);
  cudaGetSymbolAddress(&kB,   g_kB);
  cudaGetSymbolAddress(&valT, g_valT);
  cudaGetSymbolAddress(&wbuf, g_w);
  cudaGetSymbolAddress(&attsB,g_atts);
  cudaGetSymbolAddress(&catp, g_cat);

  float scale = 1.0f/sqrtf((float)HID);

  /* cat[:,0:1024] = [h, y_emb] */
  cat_copy<<<(TB*(HID/4)+255)/256, 256>>>(h, yemb);

  GP p;

  /* q = (h@Wq^T + bq)*scale -> (B,T,H) */
  p = GP{};
  p.A = h; p.B = Wq; p.C = (float*)qB;
  p.lda = HID; p.ldb = HID; p.ldc = HID;
  p.M = TB; p.N = HID; p.K = HID;
  p.bias = bq; p.alpha = scale;
  p.mode = 1; p.D1 = BATCH; p.D2 = T_LEN;
  launch_gemm<64,0>(p, 1);

  /* fused k & val projection: B rows [0,512)=Wk, [512,1024)=Wv */
  p = GP{};
  p.A = mem; p.B = Wk; p.B2 = Wv;
  p.C = (float*)kB; p.C2 = (float*)valT;
  p.lda = HID; p.ldb = HID;
  p.M = SEQ*BATCH; p.N = 2*HID; p.K = HID;
  p.bias = bk; p.bias2 = bva; p.alpha = 1.f;
  p.mode = 3;
  launch_gemm<128,1>(p, 1);

  /* scores[b]: (T,S) = q_b @ k_b^T */
  p = GP{};
  p.A = (const float*)qB; p.B = (const float*)kB; p.C = (float*)wbuf;
  p.lda = HID; p.ldb = HID; p.ldc = SEQ;
  p.sA = (long)T_LEN*HID; p.sB = (long)SEQ*HID; p.sC = (long)T_LEN*SEQ;
  p.M = T_LEN; p.N = SEQ; p.K = HID;
  p.alpha = 1.f; p.mode = 0;
  launch_gemm<64,0>(p, BATCH);

  softmax_s<<<BATCH*T_LEN, 128>>>(dists, mask);

  /* atts[b]: (T,H) = w_b @ valT_b^T */
  p = GP{};
  p.A = (const float*)wbuf; p.B = (const float*)valT; p.C = (float*)attsB;
  p.lda = SEQ; p.ldb = SEQ; p.ldc = HID;
  p.sA = (long)T_LEN*SEQ; p.sB = (long)HID*SEQ; p.sC = (long)T_LEN*HID;
  p.M = T_LEN; p.N = HID; p.K = SEQ;
  p.alpha = 1.f; p.mode = 0;
  launch_gemm<64,0>(p, BATCH);

  /* cat[:,1024:1536] = atts@Wo^T + bo  (rows b*T+t -> t*B+b) */
  p = GP{};
  p.A = (const float*)attsB; p.B = Wo; p.C = (float*)catp;
  p.lda = HID; p.ldb = HID; p.ldc = H3;
  p.M = TB; p.N = HID; p.K = HID;
  p.bias = bo; p.alpha = 1.f;
  p.mode = 1; p.D1 = T_LEN; p.D2 = BATCH; p.col_off = 1024;
  launch_gemm<64,0>(p, 1);

  /* logits = cat@Wp^T + bp -> d_out rows, ldc = V+EXT */
  p = GP{};
  p.A = (const float*)catp; p.B = Wp; p.C = out;
  p.lda = H3; p.ldb = H3; p.ldc = VE;
  p.M = TB; p.N = VOC; p.K = H3;
  p.bias = bp; p.alpha = 1.f; p.mode = 0;
  launch_gemm<128,0>(p, 1);

  /* fused gate + softmax over V + ext zero + scatter */
  softmax_v<<<TB, 512>>>(out, xids, vv, bv);

  (void)out_size; (void)n_in;
}

// round 6
// speedup vs baseline: 1.5180x; 1.0218x over previous
#include <cuda_runtime.h>
#include <math.h>
#include <stdint.h>

#define T_LEN 64
#define BATCH 32
#define SEQ   400
#define HID   512
#define VOC   50000
#define EXTD  400
#define VE    (VOC+EXTD)
#define TB    (T_LEN*BATCH)     /* 2048 */
#define H3    (3*HID)           /* 1536 */

/* ---------------- scratch (device globals: allocation-free) -------------- */
__device__ float g_cat [TB*H3];             /* (T*B, 3H) rows t*B+b          */
__device__ float g_qB  [BATCH*T_LEN*HID];   /* (B,T,H)                       */
__device__ float g_kB  [BATCH*SEQ*HID];     /* (B,S,H)                       */
__device__ float g_valT[BATCH*HID*SEQ];     /* (B,H,S)                       */
__device__ float g_w   [BATCH*T_LEN*SEQ];   /* (B,T,S) attn weights          */
__device__ float g_atts[TB*HID];            /* (B,T,H) rows b*T+t            */

/* ---------------- generic TF32 MMA GEMM: C = alpha*(A@B^T + bias) -------- */
struct GP {
  const float* A; const float* B; const float* B2;
  float* C; float* C2;
  long lda, ldb, ldc;
  long sA, sB, sC;            /* batch strides (grid.z)                      */
  int  M, N, K;
  const float* bias; const float* bias2;
  float alpha;
  int  mode, D1, D2;          /* epilogue index modes                        */
  long col_off;
};

#define BN 128
#define BK 32

__device__ __forceinline__ void cpa16u(unsigned dst, const float* src, int bytes){
  asm volatile("cp.async.cg.shared.global [%0], [%1], 16, %2;\n"
               :: "r"(dst), "l"(src), "r"(bytes));
}
#define CPA_COMMIT() asm volatile("cp.async.commit_group;\n")
#define CPA_WAIT2()  asm volatile("cp.async.wait_group 2;\n")
#define CPA_WAIT1()  asm volatile("cp.async.wait_group 1;\n")

#define LDSM_X4(r0,r1,r2,r3,addr) \
  asm volatile("ldmatrix.sync.aligned.m8n8.x4.shared.b16 {%0,%1,%2,%3}, [%4];" \
               : "=r"(r0), "=r"(r1), "=r"(r2), "=r"(r3) : "r"(addr))

#define MMA8(d, a0,a1,a2,a3, b0,b1) \
  asm volatile("mma.sync.aligned.m16n8k8.row.col.f32.tf32.tf32.f32 " \
               "{%0,%1,%2,%3}, {%4,%5,%6,%7}, {%8,%9}, {%0,%1,%2,%3};\n" \
               : "+f"((d)[0]), "+f"((d)[1]), "+f"((d)[2]), "+f"((d)[3]) \
               : "r"(a0), "r"(a1), "r"(a2), "r"(a3), "r"(b0), "r"(b1))

__device__ __forceinline__ void epi(const GP& p, float* C, int m, int n, float v){
  if (m >= p.M || n >= p.N) return;
  if (p.mode == 3){                    /* fused k/val projection epilogue    */
    int s = m / BATCH, b = m % BATCH;
    if (n < HID){                      /* k -> (B,S,H) */
      p.C[((long)b*SEQ + s)*HID + n] = v + p.bias[n];
    } else {                           /* val -> (B,H,S) */
      int nn = n - HID;
      p.C2[((long)b*HID + nn)*SEQ + s] = v + p.bias2[nn];
    }
    return;
  }
  float bb = p.bias ? p.bias[n] : 0.f;
  float o = p.alpha * (v + bb);
  long idx;
  if (p.mode == 0)      idx = (long)m * p.ldc + p.col_off + n;
  else                  idx = (long)((m % p.D1) * p.D2 + m / p.D1) * p.ldc + p.col_off + n;
  C[idx] = o;
}

template<int BMT, int DUAL>
__global__ __launch_bounds__(256) void gemm_tf32(GP p){
  constexpr int WM   = BMT/32;         /* warp rows: 4 or 2                  */
  constexpr int NCOL = BN/(8/WM);      /* warp cols: 64 or 32                */
  constexpr int NFR  = NCOL/8;         /* n frags:   8 or 4                  */
  constexpr int NBL  = NCOL/16;        /* B ldsm.x4: 4 or 2                  */
  constexpr int ABYT = BMT*BK*4;
  constexpr int SBYT = ABYT + BN*BK*4;
  constexpr int GT   = (BMT+BN)*8;     /* 16B granules per stage             */

  extern __shared__ float smf[];
  uint32_t sbase = (uint32_t)__cvta_generic_to_shared(smf);
  const float* A  = p.A + (long)blockIdx.z * p.sA;
  const float* Bg = p.B + (long)blockIdx.z * p.sB;
  float*       C  = p.C + (long)blockIdx.z * p.sC;

  int tid = threadIdx.x;
  int lane = tid & 31, warp = tid >> 5;
  int wm = warp % WM, wn = warp / WM;
  int m0 = blockIdx.x * BMT, n0 = blockIdx.y * BN;

  float acc[2][NFR][4];
  #pragma unroll
  for (int i=0;i<2;i++)
    #pragma unroll
    for (int j=0;j<NFR;j++){ acc[i][j][0]=0.f; acc[i][j][1]=0.f; acc[i][j][2]=0.f; acc[i][j][3]=0.f; }

  int ktiles = (p.K + BK - 1)/BK;

  auto load = [&](int st, int k0){
    uint32_t ab = sbase + st*SBYT;
    uint32_t bb = ab + ABYT;
    #pragma unroll
    for (int i=0;i<GT/256;i++){
      int g = tid + i*256;
      int r = g >> 3, gc = g & 7;
      int kcol = k0 + gc*4;
      int kleft = p.K - kcol;
      int kb = (kleft >= 4) ? 16 : (kleft > 0 ? kleft*4 : 0);
      if (r < BMT){
        uint32_t soff = (uint32_t)(r*128 + ((gc ^ (r&7))<<4));
        int gm = m0 + r;
        cpa16u(ab + soff, A + (long)gm*p.lda + kcol, (gm < p.M) ? kb : 0);
      } else {
        int rb = r - BMT;
        uint32_t soff = (uint32_t)(rb*128 + ((gc ^ (rb&7))<<4));
        int gn = n0 + rb;
        const float* src;
        if (DUAL && gn >= HID) src = p.B2 + (long)(gn-HID)*p.ldb + kcol;
        else                   src = Bg  + (long)gn*p.ldb + kcol;
        cpa16u(bb + soff, src, (gn < p.N) ? kb : 0);
      }
    }
  };

  load(0, 0); CPA_COMMIT();
  load(1, BK); CPA_COMMIT();

  int mi1 = (lane >> 3) & 1;
  int kg2 = lane >> 4;
  int ri  = lane & 7;
  int marow = wm*32 + mi1*8 + ri;
  int nbrow = wn*NCOL + mi1*8 + ri;
  int maxor = (marow & 7);
  int nbxor = (nbrow & 7);

  /* R3-proven pipeline: issue -> commit -> wait2 -> sync -> compute -> sync */
  for (int kt = 0; kt < ktiles; kt++){
    if (kt + 2 < ktiles) load((kt+2)%3, (kt+2)*BK);
    CPA_COMMIT();
    CPA_WAIT2();
    __syncthreads();

    uint32_t ab = sbase + (kt%3)*SBYT;
    uint32_t aA = ab + marow*128;
    uint32_t aB = ab + ABYT + nbrow*128;

    #pragma unroll
    for (int kk=0; kk<4; kk++){
      uint32_t asw = (uint32_t)(((kk*2 + kg2) ^ maxor) << 4);
      uint32_t bsw = (uint32_t)(((kk*2 + kg2) ^ nbxor) << 4);
      unsigned af0[4], af1[4], bf[NBL][4];
      LDSM_X4(af0[0],af0[1],af0[2],af0[3], aA + asw);
      LDSM_X4(af1[0],af1[1],af1[2],af1[3], aA + asw + 16*128);
      #pragma unroll
      for (int jp=0; jp<NBL; jp++)
        LDSM_X4(bf[jp][0],bf[jp][1],bf[jp][2],bf[jp][3], aB + bsw + jp*16*128);
      #pragma unroll
      for (int jp=0; jp<NBL; jp++){
        MMA8(acc[0][2*jp  ], af0[0],af0[1],af0[2],af0[3], bf[jp][0], bf[jp][2]);
        MMA8(acc[0][2*jp+1], af0[0],af0[1],af0[2],af0[3], bf[jp][1], bf[jp][3]);
        MMA8(acc[1][2*jp  ], af1[0],af1[1],af1[2],af1[3], bf[jp][0], bf[jp][2]);
        MMA8(acc[1][2*jp+1], af1[0],af1[1],af1[2],af1[3], bf[jp][1], bf[jp][3]);
      }
    }
    __syncthreads();
  }

  int r = lane >> 2, c2 = (lane & 3)*2;
  #pragma unroll
  for (int im=0; im<2; im++)
    #pragma unroll
    for (int jn=0; jn<NFR; jn++){
      int mr = m0 + wm*32 + im*16 + r;
      int nc = n0 + wn*NCOL + jn*8 + c2;
      epi(p, C, mr,   nc,   acc[im][jn][0]);
      epi(p, C, mr,   nc+1, acc[im][jn][1]);
      epi(p, C, mr+8, nc,   acc[im][jn][2]);
      epi(p, C, mr+8, nc+1, acc[im][jn][3]);
    }
}

/* ====== specialized Wp GEMM: 128x256 CTA tile, 64x64 warp tile =========== */
/* out[m,n] = cat[m,:].Wp[n,:] + bp[n];  M=2048, N=50000(pad 50176), K=1536  */
#define WBM 128
#define WBN 256
#define WABY (WBM*BK*4)                 /* 16384 */
#define WSBY (WABY + WBN*BK*4)          /* 49152 per stage */
#define WSMEM (2*WSBY)                  /* 98304 */

__global__ __launch_bounds__(256) void gemm_wp(
    const float* __restrict__ A, const float* __restrict__ B,
    const float* __restrict__ bias, float* __restrict__ out)
{
  extern __shared__ float smf[];
  uint32_t sbase = (uint32_t)__cvta_generic_to_shared(smf);
  int tid = threadIdx.x;
  int lane = tid & 31, warp = tid >> 5;
  int wm = warp & 1, wn = warp >> 1;     /* 2 x 4 warp grid, 64x64 tiles     */
  int m0 = blockIdx.x * WBM, n0 = blockIdx.y * WBN;

  float acc[4][8][4];
  #pragma unroll
  for (int i=0;i<4;i++)
    #pragma unroll
    for (int j=0;j<8;j++){ acc[i][j][0]=0.f; acc[i][j][1]=0.f; acc[i][j][2]=0.f; acc[i][j][3]=0.f; }

  const int ktiles = H3/BK;              /* 48 */

  auto load = [&](int st, int k0){
    uint32_t ab = sbase + st*WSBY;
    uint32_t bb = ab + WABY;
    #pragma unroll
    for (int i=0;i<12;i++){              /* (128+256)*8 / 256 granules       */
      int g = tid + i*256;
      int r = g >> 3, gc = g & 7;
      int kcol = k0 + gc*4;
      if (r < WBM){
        uint32_t soff = (uint32_t)(r*128 + ((gc ^ (r&7))<<4));
        cpa16u(ab + soff, A + (long)(m0 + r)*H3 + kcol, 16);
      } else {
        int rb = r - WBM;
        uint32_t soff = (uint32_t)(rb*128 + ((gc ^ (rb&7))<<4));
        int gn = n0 + rb;
        int ok = gn < VOC;
        cpa16u(bb + soff, B + (long)(ok ? gn : 0)*H3 + kcol, ok ? 16 : 0);
      }
    }
  };

  load(0, 0); CPA_COMMIT();

  int mi1 = (lane >> 3) & 1;
  int kg2 = lane >> 4;
  int ri  = lane & 7;
  int marow = wm*64 + mi1*8 + ri;
  int nbrow = wn*64 + mi1*8 + ri;
  int maxor = (marow & 7);
  int nbxor = (nbrow & 7);

  for (int kt = 0; kt < ktiles; kt++){
    if (kt + 1 < ktiles) load((kt+1)&1, (kt+1)*BK);
    CPA_COMMIT();
    CPA_WAIT1();
    __syncthreads();

    uint32_t ab = sbase + (kt&1)*WSBY;
    uint32_t aA = ab + marow*128;
    uint32_t aB = ab + WABY + nbrow*128;

    #pragma unroll
    for (int kk=0; kk<4; kk++){
      uint32_t asw = (uint32_t)(((kk*2 + kg2) ^ maxor) << 4);
      uint32_t bsw = (uint32_t)(((kk*2 + kg2) ^ nbxor) << 4);
      unsigned af[4][4], bf[4][4];
      #pragma unroll
      for (int mi=0; mi<4; mi++)
        LDSM_X4(af[mi][0],af[mi][1],af[mi][2],af[mi][3], aA + asw + mi*16*128);
      #pragma unroll
      for (int jb=0; jb<4; jb++)
        LDSM_X4(bf[jb][0],bf[jb][1],bf[jb][2],bf[jb][3], aB + bsw + jb*16*128);
      #pragma unroll
      for (int mi=0; mi<4; mi++)
        #pragma unroll
        for (int jb=0; jb<4; jb++){
          MMA8(acc[mi][2*jb  ], af[mi][0],af[mi][1],af[mi][2],af[mi][3], bf[jb][0], bf[jb][2]);
          MMA8(acc[mi][2*jb+1], af[mi][0],af[mi][1],af[mi][2],af[mi][3], bf[jb][1], bf[jb][3]);
        }
    }
    __syncthreads();
  }

  int r2 = lane >> 2, c2 = (lane & 3)*2;
  #pragma unroll
  for (int mi=0; mi<4; mi++)
    #pragma unroll
    for (int nj=0; nj<8; nj++){
      int mr = m0 + wm*64 + mi*16 + r2;
      int nc = n0 + wn*64 + nj*8 + c2;
      if (nc < VOC){                     /* nc even, VOC even -> nc+1 ok too */
        float b0 = bias[nc], b1 = bias[nc+1];
        float* o0 = out + (long)mr*VE + nc;
        float* o1 = out + (long)(mr+8)*VE + nc;
        o0[0] = acc[mi][nj][0] + b0;  o0[1] = acc[mi][nj][1] + b1;
        o1[0] = acc[mi][nj][2] + b0;  o1[1] = acc[mi][nj][3] + b1;
      }
    }
}

/* ---------------- cat[:, 0:1024] = [h, y_emb] ---------------------------- */
__global__ void cat_copy(const float* __restrict__ h, const float* __restrict__ y){
  int i = blockIdx.x*blockDim.x + threadIdx.x;
  if (i >= TB*(HID/4)) return;
  int row = i / (HID/4);
  int c   = i % (HID/4);
  const float4* h4 = (const float4*)h;
  const float4* y4 = (const float4*)y;
  float4* cat4 = (float4*)g_cat;
  cat4[(long)row*(H3/4) + c]           = h4[i];
  cat4[(long)row*(H3/4) + (HID/4) + c] = y4[i];
}

/* ---------------- softmax over S; writes w (B,T,S) + dists (T,B,S) ------- */
__global__ void softmax_s(float* __restrict__ dists, const unsigned char* __restrict__ mask){
  int bt = blockIdx.x;                  /* b*T + t */
  int b = bt / T_LEN, t = bt % T_LEN;
  float* row = g_w + (long)bt*SEQ;
  const unsigned char* mrow = mask + (long)b*SEQ;
  int tid = threadIdx.x;                /* 128 */
  __shared__ float red[128];
  float mx = -1e30f;
  for (int s=tid; s<SEQ; s+=128){
    float x = mrow[s] ? -1e9f : row[s];
    mx = fmaxf(mx, x);
  }
  red[tid]=mx; __syncthreads();
  for (int off=64; off>0; off>>=1){ if (tid<off) red[tid]=fmaxf(red[tid],red[tid+off]); __syncthreads(); }
  mx = red[0]; __syncthreads();
  float sum=0.f;
  for (int s=tid; s<SEQ; s+=128){
    float x = mrow[s] ? -1e9f : row[s];
    sum += __expf(x-mx);
  }
  red[tid]=sum; __syncthreads();
  for (int off=64; off>0; off>>=1){ if (tid<off) red[tid]+=red[tid+off]; __syncthreads(); }
  float inv = 1.f/red[0];
  for (int s=tid; s<SEQ; s+=128){
    float x = mrow[s] ? -1e9f : row[s];
    float wv = __expf(x-mx)*inv;
    row[s] = wv;
    dists[((long)t*BATCH + b)*SEQ + s] = wv;
  }
}

/* -------- fused: gate + softmax over V + ext zero + pointer scatter ------ */
__global__ void softmax_v(float* __restrict__ out, const int* __restrict__ xids,
                          const float* __restrict__ vv, const float* __restrict__ bvv){
  int rid = blockIdx.x;                 /* t*B + b */
  int b = rid % BATCH, t = rid / BATCH;
  float* row = out + (long)rid*VE;
  int tid = threadIdx.x;                /* 512 */
  __shared__ float rm[512], rs[512];
  __shared__ float gsh;

  /* gate = sigmoid(cat[rid] . v + bv) */
  const float* cr = g_cat + (long)rid*H3;
  float s0 = 0.f;
  for (int j=tid; j<H3; j+=512) s0 += cr[j]*vv[j];
  rm[tid]=s0; __syncthreads();
  for (int off=256; off>0; off>>=1){ if (tid<off) rm[tid]+=rm[tid+off]; __syncthreads(); }
  if (tid==0) gsh = 1.f/(1.f+__expf(-(rm[0]+bvv[0])));
  __syncthreads();
  float g = gsh;

  /* online softmax over V */
  float m = row[tid], s = 1.f;
  for (int j=tid+512; j<VOC; j+=512){
    float x = row[j];
    if (x > m){ s = s*__expf(m-x) + 1.f; m = x; }
    else        s += __expf(x-m);
  }
  rm[tid]=m; rs[tid]=s; __syncthreads();
  for (int off=256; off>0; off>>=1){
    if (tid<off){
      float m2=rm[tid+off], s2=rs[tid+off];
      float M=fmaxf(rm[tid],m2);
      rs[tid]=rs[tid]*__expf(rm[tid]-M)+s2*__expf(m2-M);
      rm[tid]=M;
    }
    __syncthreads();
  }
  float M = rm[0];
  float gscale = g/rs[0];
  for (int j=tid; j<VOC; j+=512) row[j] = __expf(row[j]-M)*gscale;
  for (int j=VOC+tid; j<VE; j+=512) row[j] = 0.f;

  /* order the stores before cross-thread atomics on the same row */
  __threadfence(); __syncthreads();

  float omg = 1.f - g;
  for (int si=tid; si<SEQ; si+=512){
    float wv = g_w[((long)b*T_LEN + t)*SEQ + si];
    int col = xids[(long)si*BATCH + b];
    atomicAdd(row + col, omg*wv);
  }
}

/* ------------------------------- host ----------------------------------- */
template<int BMT, int DUAL>
static inline void launch_gemm(const GP& p, int batches){
  constexpr int SM = 3*((BMT+BN)*BK*4);
  static bool done = false;
  if (!done){
    cudaFuncSetAttribute(gemm_tf32<BMT,DUAL>,
                         cudaFuncAttributeMaxDynamicSharedMemorySize, SM);
    done = true;
  }
  dim3 grid((p.M+BMT-1)/BMT, (p.N+BN-1)/BN, batches);
  gemm_tf32<BMT,DUAL><<<grid, 256, SM>>>(p);
}

extern "C" void kernel_launch(void* const* d_in, const int* in_sizes, int n_in,
                              void* d_out, int out_size){
  const float* h    = (const float*)d_in[0];
  const float* yemb = (const float*)d_in[1];
  const float* mem  = (const float*)d_in[2];
  const unsigned char* mask = (const unsigned char*)d_in[3];
  const int* xids   = (const int*)d_in[4];
  int wb = 5;
  if (n_in >= 18 && in_sizes[5] == 1) wb = 6;   /* max_ext_len scalar present */
  const float* Wq = (const float*)d_in[wb+0];
  const float* bq = (const float*)d_in[wb+1];
  const float* Wk = (const float*)d_in[wb+2];
  const float* bk = (const float*)d_in[wb+3];
  const float* Wv = (const float*)d_in[wb+4];
  const float* bva= (const float*)d_in[wb+5];
  const float* Wo = (const float*)d_in[wb+6];
  const float* bo = (const float*)d_in[wb+7];
  const float* Wp = (const float*)d_in[wb+8];
  const float* bp = (const float*)d_in[wb+9];
  const float* vv = (const float*)d_in[wb+10];
  const float* bv = (const float*)d_in[wb+11];

  float* out   = (float*)d_out;
  float* dists = out + (long)TB*VE;

  cudaFuncSetAttribute(gemm_wp, cudaFuncAttributeMaxDynamicSharedMemorySize, WSMEM);

  void *qB, *kB, *valT, *wbuf, *attsB, *catp;
  cudaGetSymbolAddress(&qB,   g_qB);
  cudaGetSymbolAddress(&kB,   g_kB);
  cudaGetSymbolAddress(&valT, g_valT);
  cudaGetSymbolAddress(&wbuf, g_w);
  cudaGetSymbolAddress(&attsB,g_atts);
  cudaGetSymbolAddress(&catp, g_cat);

  float scale = 1.0f/sqrtf((float)HID);

  /* cat[:,0:1024] = [h, y_emb] */
  cat_copy<<<(TB*(HID/4)+255)/256, 256>>>(h, yemb);

  GP p;

  /* q = (h@Wq^T + bq)*scale -> (B,T,H) */
  p = GP{};
  p.A = h; p.B = Wq; p.C = (float*)qB;
  p.lda = HID; p.ldb = HID; p.ldc = HID;
  p.M = TB; p.N = HID; p.K = HID;
  p.bias = bq; p.alpha = scale;
  p.mode = 1; p.D1 = BATCH; p.D2 = T_LEN;
  launch_gemm<64,0>(p, 1);

  /* fused k & val projection: B rows [0,512)=Wk, [512,1024)=Wv */
  p = GP{};
  p.A = mem; p.B = Wk; p.B2 = Wv;
  p.C = (float*)kB; p.C2 = (float*)valT;
  p.lda = HID; p.ldb = HID;
  p.M = SEQ*BATCH; p.N = 2*HID; p.K = HID;
  p.bias = bk; p.bias2 = bva; p.alpha = 1.f;
  p.mode = 3;
  launch_gemm<128,1>(p, 1);

  /* scores[b]: (T,S) = q_b @ k_b^T */
  p = GP{};
  p.A = (const float*)qB; p.B = (const float*)kB; p.C = (float*)wbuf;
  p.lda = HID; p.ldb = HID; p.ldc = SEQ;
  p.sA = (long)T_LEN*HID; p.sB = (long)SEQ*HID; p.sC = (long)T_LEN*SEQ;
  p.M = T_LEN; p.N = SEQ; p.K = HID;
  p.alpha = 1.f; p.mode = 0;
  launch_gemm<64,0>(p, BATCH);

  softmax_s<<<BATCH*T_LEN, 128>>>(dists, mask);

  /* atts[b]: (T,H) = w_b @ valT_b^T */
  p = GP{};
  p.A = (const float*)wbuf; p.B = (const float*)valT; p.C = (float*)attsB;
  p.lda = SEQ; p.ldb = SEQ; p.ldc = HID;
  p.sA = (long)T_LEN*SEQ; p.sB = (long)HID*SEQ; p.sC = (long)T_LEN*HID;
  p.M = T_LEN; p.N = HID; p.K = SEQ;
  p.alpha = 1.f; p.mode = 0;
  launch_gemm<64,0>(p, BATCH);

  /* cat[:,1024:1536] = atts@Wo^T + bo  (rows b*T+t -> t*B+b) */
  p = GP{};
  p.A = (const float*)attsB; p.B = Wo; p.C = (float*)catp;
  p.lda = HID; p.ldb = HID; p.ldc = H3;
  p.M = TB; p.N = HID; p.K = HID;
  p.bias = bo; p.alpha = 1.f;
  p.mode = 1; p.D1 = T_LEN; p.D2 = BATCH; p.col_off = 1024;
  launch_gemm<64,0>(p, 1);

  /* logits = cat@Wp^T + bp -> d_out rows (specialized 128x256 kernel) */
  gemm_wp<<<dim3(TB/WBM, (VOC + WBN - 1)/WBN), 256, WSMEM>>>(
      (const float*)catp, Wp, bp, out);

  /* fused gate + softmax over V + ext zero + scatter */
  softmax_v<<<TB, 512>>>(out, xids, vv, bv);

  (void)out_size; (void)n_in;
}

// round 7
// speedup vs baseline: 1.5426x; 1.0162x over previous
#include <cuda_runtime.h>
#include <math.h>
#include <stdint.h>

#define T_LEN 64
#define BATCH 32
#define SEQ   400
#define HID   512
#define VOC   50000
#define EXTD  400
#define VE    (VOC+EXTD)
#define TB    (T_LEN*BATCH)     /* 2048 */
#define H3    (3*HID)           /* 1536 */

/* ---------------- scratch (device globals: allocation-free) -------------- */
__device__ float g_cat [TB*H3];             /* (T*B, 3H) rows t*B+b          */
__device__ float g_qB  [BATCH*T_LEN*HID];   /* (B,T,H)                       */
__device__ float g_kB  [BATCH*SEQ*HID];     /* (B,S,H)                       */
__device__ float g_valT[BATCH*HID*SEQ];     /* (B,H,S)                       */
__device__ float g_w   [BATCH*T_LEN*SEQ];   /* (B,T,S) attn weights          */
__device__ float g_atts[TB*HID];            /* (B,T,H) rows b*T+t            */

/* ---------------- generic TF32 MMA GEMM: C = alpha*(A@B^T + bias) -------- */
struct GP {
  const float* A; const float* B; const float* B2;
  float* C; float* C2;
  long lda, ldb, ldc;
  long sA, sB, sC;            /* batch strides (grid.z)                      */
  int  M, N, K;
  const float* bias; const float* bias2;
  float alpha;
  int  mode, D1, D2;          /* epilogue index modes                        */
  long col_off;
};

#define BN 128
#define BK 32

__device__ __forceinline__ void cpa16u(unsigned dst, const float* src, int bytes){
  asm volatile("cp.async.cg.shared.global [%0], [%1], 16, %2;\n"
               :: "r"(dst), "l"(src), "r"(bytes));
}
#define CPA_COMMIT() asm volatile("cp.async.commit_group;\n")
#define CPA_WAIT2()  asm volatile("cp.async.wait_group 2;\n")

#define LDSM_X4(r0,r1,r2,r3,addr) \
  asm volatile("ldmatrix.sync.aligned.m8n8.x4.shared.b16 {%0,%1,%2,%3}, [%4];" \
               : "=r"(r0), "=r"(r1), "=r"(r2), "=r"(r3) : "r"(addr))

#define MMA8(d, a0,a1,a2,a3, b0,b1) \
  asm volatile("mma.sync.aligned.m16n8k8.row.col.f32.tf32.tf32.f32 " \
               "{%0,%1,%2,%3}, {%4,%5,%6,%7}, {%8,%9}, {%0,%1,%2,%3};\n" \
               : "+f"((d)[0]), "+f"((d)[1]), "+f"((d)[2]), "+f"((d)[3]) \
               : "r"(a0), "r"(a1), "r"(a2), "r"(a3), "r"(b0), "r"(b1))

__device__ __forceinline__ void epi(const GP& p, float* C, int m, int n, float v){
  if (m >= p.M || n >= p.N) return;
  if (p.mode == 3){                    /* fused k/val projection epilogue    */
    int s = m / BATCH, b = m % BATCH;
    if (n < HID){                      /* k -> (B,S,H) */
      p.C[((long)b*SEQ + s)*HID + n] = v + p.bias[n];
    } else {                           /* val -> (B,H,S) */
      int nn = n - HID;
      p.C2[((long)b*HID + nn)*SEQ + s] = v + p.bias2[nn];
    }
    return;
  }
  float bb = p.bias ? p.bias[n] : 0.f;
  float o = p.alpha * (v + bb);
  long idx;
  if (p.mode == 0)      idx = (long)m * p.ldc + p.col_off + n;
  else                  idx = (long)((m % p.D1) * p.D2 + m / p.D1) * p.ldc + p.col_off + n;
  C[idx] = o;
}

template<int BMT, int DUAL>
__global__ __launch_bounds__(256) void gemm_tf32(GP p){
  constexpr int WM   = BMT/32;         /* warp rows: 4 or 2                  */
  constexpr int NCOL = BN/(8/WM);      /* warp cols: 64 or 32                */
  constexpr int NFR  = NCOL/8;         /* n frags:   8 or 4                  */
  constexpr int NBL  = NCOL/16;        /* B ldsm.x4: 4 or 2                  */
  constexpr int ABYT = BMT*BK*4;
  constexpr int SBYT = ABYT + BN*BK*4;
  constexpr int GT   = (BMT+BN)*8;     /* 16B granules per stage             */

  extern __shared__ float smf[];
  uint32_t sbase = (uint32_t)__cvta_generic_to_shared(smf);
  const float* A  = p.A + (long)blockIdx.z * p.sA;
  const float* Bg = p.B + (long)blockIdx.z * p.sB;
  float*       C  = p.C + (long)blockIdx.z * p.sC;

  int tid = threadIdx.x;
  int lane = tid & 31, warp = tid >> 5;
  int wm = warp % WM, wn = warp / WM;
  int m0 = blockIdx.x * BMT, n0 = blockIdx.y * BN;

  float acc[2][NFR][4];
  #pragma unroll
  for (int i=0;i<2;i++)
    #pragma unroll
    for (int j=0;j<NFR;j++){ acc[i][j][0]=0.f; acc[i][j][1]=0.f; acc[i][j][2]=0.f; acc[i][j][3]=0.f; }

  int ktiles = (p.K + BK - 1)/BK;

  auto load = [&](int st, int k0){
    uint32_t ab = sbase + st*SBYT;
    uint32_t bb = ab + ABYT;
    #pragma unroll
    for (int i=0;i<GT/256;i++){
      int g = tid + i*256;
      int r = g >> 3, gc = g & 7;
      int kcol = k0 + gc*4;
      int kleft = p.K - kcol;
      int kb = (kleft >= 4) ? 16 : (kleft > 0 ? kleft*4 : 0);
      if (r < BMT){
        uint32_t soff = (uint32_t)(r*128 + ((gc ^ (r&7))<<4));
        int gm = m0 + r;
        cpa16u(ab + soff, A + (long)gm*p.lda + kcol, (gm < p.M) ? kb : 0);
      } else {
        int rb = r - BMT;
        uint32_t soff = (uint32_t)(rb*128 + ((gc ^ (rb&7))<<4));
        int gn = n0 + rb;
        const float* src;
        if (DUAL && gn >= HID) src = p.B2 + (long)(gn-HID)*p.ldb + kcol;
        else                   src = Bg  + (long)gn*p.ldb + kcol;
        cpa16u(bb + soff, src, (gn < p.N) ? kb : 0);
      }
    }
  };

  load(0, 0); CPA_COMMIT();
  load(1, BK); CPA_COMMIT();

  int mi1 = (lane >> 3) & 1;
  int kg2 = lane >> 4;
  int ri  = lane & 7;
  int marow = wm*32 + mi1*8 + ri;
  int nbrow = wn*NCOL + mi1*8 + ri;
  int maxor = (marow & 7);
  int nbxor = (nbrow & 7);

  /* R3-proven pipeline: issue -> commit -> wait2 -> sync -> compute -> sync */
  for (int kt = 0; kt < ktiles; kt++){
    if (kt + 2 < ktiles) load((kt+2)%3, (kt+2)*BK);
    CPA_COMMIT();
    CPA_WAIT2();
    __syncthreads();

    uint32_t ab = sbase + (kt%3)*SBYT;
    uint32_t aA = ab + marow*128;
    uint32_t aB = ab + ABYT + nbrow*128;

    #pragma unroll
    for (int kk=0; kk<4; kk++){
      uint32_t asw = (uint32_t)(((kk*2 + kg2) ^ maxor) << 4);
      uint32_t bsw = (uint32_t)(((kk*2 + kg2) ^ nbxor) << 4);
      unsigned af0[4], af1[4], bf[NBL][4];
      LDSM_X4(af0[0],af0[1],af0[2],af0[3], aA + asw);
      LDSM_X4(af1[0],af1[1],af1[2],af1[3], aA + asw + 16*128);
      #pragma unroll
      for (int jp=0; jp<NBL; jp++)
        LDSM_X4(bf[jp][0],bf[jp][1],bf[jp][2],bf[jp][3], aB + bsw + jp*16*128);
      #pragma unroll
      for (int jp=0; jp<NBL; jp++){
        MMA8(acc[0][2*jp  ], af0[0],af0[1],af0[2],af0[3], bf[jp][0], bf[jp][2]);
        MMA8(acc[0][2*jp+1], af0[0],af0[1],af0[2],af0[3], bf[jp][1], bf[jp][3]);
        MMA8(acc[1][2*jp  ], af1[0],af1[1],af1[2],af1[3], bf[jp][0], bf[jp][2]);
        MMA8(acc[1][2*jp+1], af1[0],af1[1],af1[2],af1[3], bf[jp][1], bf[jp][3]);
      }
    }
    __syncthreads();
  }

  int r = lane >> 2, c2 = (lane & 3)*2;
  #pragma unroll
  for (int im=0; im<2; im++)
    #pragma unroll
    for (int jn=0; jn<NFR; jn++){
      int mr = m0 + wm*32 + im*16 + r;
      int nc = n0 + wn*NCOL + jn*8 + c2;
      epi(p, C, mr,   nc,   acc[im][jn][0]);
      epi(p, C, mr,   nc+1, acc[im][jn][1]);
      epi(p, C, mr+8, nc,   acc[im][jn][2]);
      epi(p, C, mr+8, nc+1, acc[im][jn][3]);
    }
}

/* ====== specialized Wp GEMM: 128x256 CTA, 512 thr, 32x64 warp tile ======= */
/* out[m,n] = cat[m,:].Wp[n,:] + bp[n];  M=2048, N=50000, K=1536             */
#define WBM 128
#define WBN 256
#define WABY (WBM*BK*4)                 /* 16384 */
#define WSBY (WABY + WBN*BK*4)          /* 49152 per stage */
#define WSMEM (3*WSBY)                  /* 147456 */

__global__ __launch_bounds__(512,1) void gemm_wp(
    const float* __restrict__ A, const float* __restrict__ B,
    const float* __restrict__ bias, float* __restrict__ out)
{
  extern __shared__ float smf[];
  uint32_t sbase = (uint32_t)__cvta_generic_to_shared(smf);
  int tid = threadIdx.x;
  int lane = tid & 31, warp = tid >> 5;
  int wm = warp & 3, wn = warp >> 2;     /* 4 x 4 warp grid, 32x64 tiles     */
  int m0 = blockIdx.x * WBM, n0 = blockIdx.y * WBN;

  float acc[2][8][4];
  #pragma unroll
  for (int i=0;i<2;i++)
    #pragma unroll
    for (int j=0;j<8;j++){ acc[i][j][0]=0.f; acc[i][j][1]=0.f; acc[i][j][2]=0.f; acc[i][j][3]=0.f; }

  const int ktiles = H3/BK;              /* 48 */

  auto load = [&](int st, int k0){
    uint32_t ab = sbase + st*WSBY;
    uint32_t bb = ab + WABY;
    #pragma unroll
    for (int i=0;i<6;i++){               /* (128+256)*8 / 512 granules       */
      int g = tid + i*512;
      int r = g >> 3, gc = g & 7;
      int kcol = k0 + gc*4;
      if (r < WBM){
        uint32_t soff = (uint32_t)(r*128 + ((gc ^ (r&7))<<4));
        cpa16u(ab + soff, A + (long)(m0 + r)*H3 + kcol, 16);
      } else {
        int rb = r - WBM;
        uint32_t soff = (uint32_t)(rb*128 + ((gc ^ (rb&7))<<4));
        int gn = n0 + rb;
        int ok = gn < VOC;
        cpa16u(bb + soff, B + (long)(ok ? gn : 0)*H3 + kcol, ok ? 16 : 0);
      }
    }
  };

  load(0, 0); CPA_COMMIT();
  load(1, BK); CPA_COMMIT();

  int mi1 = (lane >> 3) & 1;
  int kg2 = lane >> 4;
  int ri  = lane & 7;
  int marow = wm*32 + mi1*8 + ri;
  int nbrow = wn*64 + mi1*8 + ri;
  int maxor = (marow & 7);
  int nbxor = (nbrow & 7);

  /* R3-proven pipeline ordering, 3 stages */
  for (int kt = 0; kt < ktiles; kt++){
    if (kt + 2 < ktiles) load((kt+2)%3, (kt+2)*BK);
    CPA_COMMIT();
    CPA_WAIT2();
    __syncthreads();

    uint32_t ab = sbase + (kt%3)*WSBY;
    uint32_t aA = ab + marow*128;
    uint32_t aB = ab + WABY + nbrow*128;

    #pragma unroll
    for (int kk=0; kk<4; kk++){
      uint32_t asw = (uint32_t)(((kk*2 + kg2) ^ maxor) << 4);
      uint32_t bsw = (uint32_t)(((kk*2 + kg2) ^ nbxor) << 4);
      unsigned af0[4], af1[4], bf[4][4];
      LDSM_X4(af0[0],af0[1],af0[2],af0[3], aA + asw);
      LDSM_X4(af1[0],af1[1],af1[2],af1[3], aA + asw + 16*128);
      #pragma unroll
      for (int jb=0; jb<4; jb++)
        LDSM_X4(bf[jb][0],bf[jb][1],bf[jb][2],bf[jb][3], aB + bsw + jb*16*128);
      #pragma unroll
      for (int jb=0; jb<4; jb++){
        MMA8(acc[0][2*jb  ], af0[0],af0[1],af0[2],af0[3], bf[jb][0], bf[jb][2]);
        MMA8(acc[0][2*jb+1], af0[0],af0[1],af0[2],af0[3], bf[jb][1], bf[jb][3]);
        MMA8(acc[1][2*jb  ], af1[0],af1[1],af1[2],af1[3], bf[jb][0], bf[jb][2]);
        MMA8(acc[1][2*jb+1], af1[0],af1[1],af1[2],af1[3], bf[jb][1], bf[jb][3]);
      }
    }
    __syncthreads();
  }

  int r2 = lane >> 2, c2 = (lane & 3)*2;
  #pragma unroll
  for (int im=0; im<2; im++)
    #pragma unroll
    for (int nj=0; nj<8; nj++){
      int mr = m0 + wm*32 + im*16 + r2;
      int nc = n0 + wn*64 + nj*8 + c2;
      if (nc < VOC){                     /* nc even, VOC even -> nc+1 ok too */
        float b0 = bias[nc], b1 = bias[nc+1];
        float* o0 = out + (long)mr*VE + nc;
        float* o1 = out + (long)(mr+8)*VE + nc;
        o0[0] = acc[im][nj][0] + b0;  o0[1] = acc[im][nj][1] + b1;
        o1[0] = acc[im][nj][2] + b0;  o1[1] = acc[im][nj][3] + b1;
      }
    }
}

/* ---------------- cat[:, 0:1024] = [h, y_emb] ---------------------------- */
__global__ void cat_copy(const float* __restrict__ h, const float* __restrict__ y){
  int i = blockIdx.x*blockDim.x + threadIdx.x;
  if (i >= TB*(HID/4)) return;
  int row = i / (HID/4);
  int c   = i % (HID/4);
  const float4* h4 = (const float4*)h;
  const float4* y4 = (const float4*)y;
  float4* cat4 = (float4*)g_cat;
  cat4[(long)row*(H3/4) + c]           = h4[i];
  cat4[(long)row*(H3/4) + (HID/4) + c] = y4[i];
}

/* ---------------- softmax over S; writes w (B,T,S) + dists (T,B,S) ------- */
__global__ void softmax_s(float* __restrict__ dists, const unsigned char* __restrict__ mask){
  int bt = blockIdx.x;                  /* b*T + t */
  int b = bt / T_LEN, t = bt % T_LEN;
  float* row = g_w + (long)bt*SEQ;
  const unsigned char* mrow = mask + (long)b*SEQ;
  int tid = threadIdx.x;                /* 128 */
  __shared__ float red[128];
  float mx = -1e30f;
  for (int s=tid; s<SEQ; s+=128){
    float x = mrow[s] ? -1e9f : row[s];
    mx = fmaxf(mx, x);
  }
  red[tid]=mx; __syncthreads();
  for (int off=64; off>0; off>>=1){ if (tid<off) red[tid]=fmaxf(red[tid],red[tid+off]); __syncthreads(); }
  mx = red[0]; __syncthreads();
  float sum=0.f;
  for (int s=tid; s<SEQ; s+=128){
    float x = mrow[s] ? -1e9f : row[s];
    sum += __expf(x-mx);
  }
  red[tid]=sum; __syncthreads();
  for (int off=64; off>0; off>>=1){ if (tid<off) red[tid]+=red[tid+off]; __syncthreads(); }
  float inv = 1.f/red[0];
  for (int s=tid; s<SEQ; s+=128){
    float x = mrow[s] ? -1e9f : row[s];
    float wv = __expf(x-mx)*inv;
    row[s] = wv;
    dists[((long)t*BATCH + b)*SEQ + s] = wv;
  }
}

/* -------- fused: gate + softmax over V + ext zero + pointer scatter ------ */
__global__ void softmax_v(float* __restrict__ out, const int* __restrict__ xids,
                          const float* __restrict__ vv, const float* __restrict__ bvv){
  int rid = blockIdx.x;                 /* t*B + b */
  int b = rid % BATCH, t = rid / BATCH;
  float* row = out + (long)rid*VE;
  int tid = threadIdx.x;                /* 512 */
  __shared__ float rm[512], rs[512];
  __shared__ float gsh;

  /* gate = sigmoid(cat[rid] . v + bv) */
  const float* cr = g_cat + (long)rid*H3;
  float s0 = 0.f;
  for (int j=tid; j<H3; j+=512) s0 += cr[j]*vv[j];
  rm[tid]=s0; __syncthreads();
  for (int off=256; off>0; off>>=1){ if (tid<off) rm[tid]+=rm[tid+off]; __syncthreads(); }
  if (tid==0) gsh = 1.f/(1.f+__expf(-(rm[0]+bvv[0])));
  __syncthreads();
  float g = gsh;

  /* online softmax over V */
  float m = row[tid], s = 1.f;
  for (int j=tid+512; j<VOC; j+=512){
    float x = row[j];
    if (x > m){ s = s*__expf(m-x) + 1.f; m = x; }
    else        s += __expf(x-m);
  }
  rm[tid]=m; rs[tid]=s; __syncthreads();
  for (int off=256; off>0; off>>=1){
    if (tid<off){
      float m2=rm[tid+off], s2=rs[tid+off];
      float M=fmaxf(rm[tid],m2);
      rs[tid]=rs[tid]*__expf(rm[tid]-M)+s2*__expf(m2-M);
      rm[tid]=M;
    }
    __syncthreads();
  }
  float M = rm[0];
  float gscale = g/rs[0];
  for (int j=tid; j<VOC; j+=512) row[j] = __expf(row[j]-M)*gscale;
  for (int j=VOC+tid; j<VE; j+=512) row[j] = 0.f;

  /* order the stores before cross-thread atomics on the same row */
  __threadfence(); __syncthreads();

  float omg = 1.f - g;
  for (int si=tid; si<SEQ; si+=512){
    float wv = g_w[((long)b*T_LEN + t)*SEQ + si];
    int col = xids[(long)si*BATCH + b];
    atomicAdd(row + col, omg*wv);
  }
}

/* ------------------------------- host ----------------------------------- */
template<int BMT, int DUAL>
static inline void launch_gemm(const GP& p, int batches){
  constexpr int SM = 3*((BMT+BN)*BK*4);
  static bool done = false;
  if (!done){
    cudaFuncSetAttribute(gemm_tf32<BMT,DUAL>,
                         cudaFuncAttributeMaxDynamicSharedMemorySize, SM);
    done = true;
  }
  dim3 grid((p.M+BMT-1)/BMT, (p.N+BN-1)/BN, batches);
  gemm_tf32<BMT,DUAL><<<grid, 256, SM>>>(p);
}

extern "C" void kernel_launch(void* const* d_in, const int* in_sizes, int n_in,
                              void* d_out, int out_size){
  const float* h    = (const float*)d_in[0];
  const float* yemb = (const float*)d_in[1];
  const float* mem  = (const float*)d_in[2];
  const unsigned char* mask = (const unsigned char*)d_in[3];
  const int* xids   = (const int*)d_in[4];
  int wb = 5;
  if (n_in >= 18 && in_sizes[5] == 1) wb = 6;   /* max_ext_len scalar present */
  const float* Wq = (const float*)d_in[wb+0];
  const float* bq = (const float*)d_in[wb+1];
  const float* Wk = (const float*)d_in[wb+2];
  const float* bk = (const float*)d_in[wb+3];
  const float* Wv = (const float*)d_in[wb+4];
  const float* bva= (const float*)d_in[wb+5];
  const float* Wo = (const float*)d_in[wb+6];
  const float* bo = (const float*)d_in[wb+7];
  const float* Wp = (const float*)d_in[wb+8];
  const float* bp = (const float*)d_in[wb+9];
  const float* vv = (const float*)d_in[wb+10];
  const float* bv = (const float*)d_in[wb+11];

  float* out   = (float*)d_out;
  float* dists = out + (long)TB*VE;

  cudaFuncSetAttribute(gemm_wp, cudaFuncAttributeMaxDynamicSharedMemorySize, WSMEM);

  void *qB, *kB, *valT, *wbuf, *attsB, *catp;
  cudaGetSymbolAddress(&qB,   g_qB);
  cudaGetSymbolAddress(&kB,   g_kB);
  cudaGetSymbolAddress(&valT, g_valT);
  cudaGetSymbolAddress(&wbuf, g_w);
  cudaGetSymbolAddress(&attsB,g_atts);
  cudaGetSymbolAddress(&catp, g_cat);

  float scale = 1.0f/sqrtf((float)HID);

  /* cat[:,0:1024] = [h, y_emb] */
  cat_copy<<<(TB*(HID/4)+255)/256, 256>>>(h, yemb);

  GP p;

  /* q = (h@Wq^T + bq)*scale -> (B,T,H) */
  p = GP{};
  p.A = h; p.B = Wq; p.C = (float*)qB;
  p.lda = HID; p.ldb = HID; p.ldc = HID;
  p.M = TB; p.N = HID; p.K = HID;
  p.bias = bq; p.alpha = scale;
  p.mode = 1; p.D1 = BATCH; p.D2 = T_LEN;
  launch_gemm<64,0>(p, 1);

  /* fused k & val projection: B rows [0,512)=Wk, [512,1024)=Wv */
  p = GP{};
  p.A = mem; p.B = Wk; p.B2 = Wv;
  p.C = (float*)kB; p.C2 = (float*)valT;
  p.lda = HID; p.ldb = HID;
  p.M = SEQ*BATCH; p.N = 2*HID; p.K = HID;
  p.bias = bk; p.bias2 = bva; p.alpha = 1.f;
  p.mode = 3;
  launch_gemm<128,1>(p, 1);

  /* scores[b]: (T,S) = q_b @ k_b^T */
  p = GP{};
  p.A = (const float*)qB; p.B = (const float*)kB; p.C = (float*)wbuf;
  p.lda = HID; p.ldb = HID; p.ldc = SEQ;
  p.sA = (long)T_LEN*HID; p.sB = (long)SEQ*HID; p.sC = (long)T_LEN*SEQ;
  p.M = T_LEN; p.N = SEQ; p.K = HID;
  p.alpha = 1.f; p.mode = 0;
  launch_gemm<64,0>(p, BATCH);

  softmax_s<<<BATCH*T_LEN, 128>>>(dists, mask);

  /* atts[b]: (T,H) = w_b @ valT_b^T */
  p = GP{};
  p.A = (const float*)wbuf; p.B = (const float*)valT; p.C = (float*)attsB;
  p.lda = SEQ; p.ldb = SEQ; p.ldc = HID;
  p.sA = (long)T_LEN*SEQ; p.sB = (long)HID*SEQ; p.sC = (long)T_LEN*HID;
  p.M = T_LEN; p.N = HID; p.K = SEQ;
  p.alpha = 1.f; p.mode = 0;
  launch_gemm<64,0>(p, BATCH);

  /* cat[:,1024:1536] = atts@Wo^T + bo  (rows b*T+t -> t*B+b) */
  p = GP{};
  p.A = (const float*)attsB; p.B = Wo; p.C = (float*)catp;
  p.lda = HID; p.ldb = HID; p.ldc = H3;
  p.M = TB; p.N = HID; p.K = HID;
  p.bias = bo; p.alpha = 1.f;
  p.mode = 1; p.D1 = T_LEN; p.D2 = BATCH; p.col_off = 1024;
  launch_gemm<64,0>(p, 1);

  /* logits = cat@Wp^T + bp -> d_out rows (128x256 CTA, 512 threads) */
  gemm_wp<<<dim3(TB/WBM, (VOC + WBN - 1)/WBN), 512, WSMEM>>>(
      (const float*)catp, Wp, bp, out);

  /* fused gate + softmax over V + ext zero + scatter */
  softmax_v<<<TB, 512>>>(out, xids, vv, bv);

  (void)out_size; (void)n_in;
}

// round 8
// speedup vs baseline: 2.2859x; 1.4818x over previous
#include <cuda_runtime.h>
#include <cuda_fp16.h>
#include <math.h>
#include <stdint.h>

#define T_LEN 64
#define BATCH 32
#define SEQ   400
#define HID   512
#define VOC   50000
#define EXTD  400
#define VE    (VOC+EXTD)
#define TB    (T_LEN*BATCH)     /* 2048 */
#define H3    (3*HID)           /* 1536 */
#define VPAD  50176             /* VOC padded to 256 */

/* ---------------- scratch (device globals: allocation-free) -------------- */
__device__ float g_cat [TB*H3];             /* (T*B, 3H) rows t*B+b          */
__device__ float g_qB  [BATCH*T_LEN*HID];   /* (B,T,H)                       */
__device__ float g_kB  [BATCH*SEQ*HID];     /* (B,S,H)                       */
__device__ float g_valT[BATCH*HID*SEQ];     /* (B,H,S)                       */
__device__ float g_w   [BATCH*T_LEN*SEQ];   /* (B,T,S) attn weights          */
__device__ float g_atts[TB*HID];            /* (B,T,H) rows b*T+t            */
__device__ __half g_wp16 [(long)VPAD*H3];   /* Wp in fp16, zero-padded rows  */
__device__ __half g_cat16[TB*H3];           /* cat in fp16                   */

/* ---------------- generic TF32 MMA GEMM: C = alpha*(A@B^T + bias) -------- */
struct GP {
  const float* A; const float* B; const float* B2;
  float* C; float* C2;
  long lda, ldb, ldc;
  long sA, sB, sC;            /* batch strides (grid.z)                      */
  int  M, N, K;
  const float* bias; const float* bias2;
  float alpha;
  int  mode, D1, D2;          /* epilogue index modes                        */
  long col_off;
};

#define BN 128
#define BK 32

__device__ __forceinline__ void cpa16u(unsigned dst, const void* src, int bytes){
  asm volatile("cp.async.cg.shared.global [%0], [%1], 16, %2;\n"
               :: "r"(dst), "l"(src), "r"(bytes));
}
#define CPA_COMMIT() asm volatile("cp.async.commit_group;\n")
#define CPA_WAIT2()  asm volatile("cp.async.wait_group 2;\n")

#define LDSM_X4(r0,r1,r2,r3,addr) \
  asm volatile("ldmatrix.sync.aligned.m8n8.x4.shared.b16 {%0,%1,%2,%3}, [%4];" \
               : "=r"(r0), "=r"(r1), "=r"(r2), "=r"(r3) : "r"(addr))

#define MMA8(d, a0,a1,a2,a3, b0,b1) \
  asm volatile("mma.sync.aligned.m16n8k8.row.col.f32.tf32.tf32.f32 " \
               "{%0,%1,%2,%3}, {%4,%5,%6,%7}, {%8,%9}, {%0,%1,%2,%3};\n" \
               : "+f"((d)[0]), "+f"((d)[1]), "+f"((d)[2]), "+f"((d)[3]) \
               : "r"(a0), "r"(a1), "r"(a2), "r"(a3), "r"(b0), "r"(b1))

#define MMA16(d, a0,a1,a2,a3, b0,b1) \
  asm volatile("mma.sync.aligned.m16n8k16.row.col.f32.f16.f16.f32 " \
               "{%0,%1,%2,%3}, {%4,%5,%6,%7}, {%8,%9}, {%0,%1,%2,%3};\n" \
               : "+f"((d)[0]), "+f"((d)[1]), "+f"((d)[2]), "+f"((d)[3]) \
               : "r"(a0), "r"(a1), "r"(a2), "r"(a3), "r"(b0), "r"(b1))

__device__ __forceinline__ void epi(const GP& p, float* C, int m, int n, float v){
  if (m >= p.M || n >= p.N) return;
  if (p.mode == 3){                    /* fused k/val projection epilogue    */
    int s = m / BATCH, b = m % BATCH;
    if (n < HID){                      /* k -> (B,S,H) */
      p.C[((long)b*SEQ + s)*HID + n] = v + p.bias[n];
    } else {                           /* val -> (B,H,S) */
      int nn = n - HID;
      p.C2[((long)b*HID + nn)*SEQ + s] = v + p.bias2[nn];
    }
    return;
  }
  float bb = p.bias ? p.bias[n] : 0.f;
  float o = p.alpha * (v + bb);
  long idx;
  if (p.mode == 0)      idx = (long)m * p.ldc + p.col_off + n;
  else                  idx = (long)((m % p.D1) * p.D2 + m / p.D1) * p.ldc + p.col_off + n;
  C[idx] = o;
}

template<int BMT, int DUAL>
__global__ __launch_bounds__(256) void gemm_tf32(GP p){
  constexpr int WM   = BMT/32;         /* warp rows: 4 or 2                  */
  constexpr int NCOL = BN/(8/WM);      /* warp cols: 64 or 32                */
  constexpr int NFR  = NCOL/8;         /* n frags:   8 or 4                  */
  constexpr int NBL  = NCOL/16;        /* B ldsm.x4: 4 or 2                  */
  constexpr int ABYT = BMT*BK*4;
  constexpr int SBYT = ABYT + BN*BK*4;
  constexpr int GT   = (BMT+BN)*8;     /* 16B granules per stage             */

  extern __shared__ float smf[];
  uint32_t sbase = (uint32_t)__cvta_generic_to_shared(smf);
  const float* A  = p.A + (long)blockIdx.z * p.sA;
  const float* Bg = p.B + (long)blockIdx.z * p.sB;
  float*       C  = p.C + (long)blockIdx.z * p.sC;

  int tid = threadIdx.x;
  int lane = tid & 31, warp = tid >> 5;
  int wm = warp % WM, wn = warp / WM;
  int m0 = blockIdx.x * BMT, n0 = blockIdx.y * BN;

  float acc[2][NFR][4];
  #pragma unroll
  for (int i=0;i<2;i++)
    #pragma unroll
    for (int j=0;j<NFR;j++){ acc[i][j][0]=0.f; acc[i][j][1]=0.f; acc[i][j][2]=0.f; acc[i][j][3]=0.f; }

  int ktiles = (p.K + BK - 1)/BK;

  auto load = [&](int st, int k0){
    uint32_t ab = sbase + st*SBYT;
    uint32_t bb = ab + ABYT;
    #pragma unroll
    for (int i=0;i<GT/256;i++){
      int g = tid + i*256;
      int r = g >> 3, gc = g & 7;
      int kcol = k0 + gc*4;
      int kleft = p.K - kcol;
      int kb = (kleft >= 4) ? 16 : (kleft > 0 ? kleft*4 : 0);
      if (r < BMT){
        uint32_t soff = (uint32_t)(r*128 + ((gc ^ (r&7))<<4));
        int gm = m0 + r;
        cpa16u(ab + soff, A + (long)gm*p.lda + kcol, (gm < p.M) ? kb : 0);
      } else {
        int rb = r - BMT;
        uint32_t soff = (uint32_t)(rb*128 + ((gc ^ (rb&7))<<4));
        int gn = n0 + rb;
        const float* src;
        if (DUAL && gn >= HID) src = p.B2 + (long)(gn-HID)*p.ldb + kcol;
        else                   src = Bg  + (long)gn*p.ldb + kcol;
        cpa16u(bb + soff, src, (gn < p.N) ? kb : 0);
      }
    }
  };

  load(0, 0); CPA_COMMIT();
  load(1, BK); CPA_COMMIT();

  int mi1 = (lane >> 3) & 1;
  int kg2 = lane >> 4;
  int ri  = lane & 7;
  int marow = wm*32 + mi1*8 + ri;
  int nbrow = wn*NCOL + mi1*8 + ri;
  int maxor = (marow & 7);
  int nbxor = (nbrow & 7);

  /* R3-proven pipeline: issue -> commit -> wait2 -> sync -> compute -> sync */
  for (int kt = 0; kt < ktiles; kt++){
    if (kt + 2 < ktiles) load((kt+2)%3, (kt+2)*BK);
    CPA_COMMIT();
    CPA_WAIT2();
    __syncthreads();

    uint32_t ab = sbase + (kt%3)*SBYT;
    uint32_t aA = ab + marow*128;
    uint32_t aB = ab + ABYT + nbrow*128;

    #pragma unroll
    for (int kk=0; kk<4; kk++){
      uint32_t asw = (uint32_t)(((kk*2 + kg2) ^ maxor) << 4);
      uint32_t bsw = (uint32_t)(((kk*2 + kg2) ^ nbxor) << 4);
      unsigned af0[4], af1[4], bf[NBL][4];
      LDSM_X4(af0[0],af0[1],af0[2],af0[3], aA + asw);
      LDSM_X4(af1[0],af1[1],af1[2],af1[3], aA + asw + 16*128);
      #pragma unroll
      for (int jp=0; jp<NBL; jp++)
        LDSM_X4(bf[jp][0],bf[jp][1],bf[jp][2],bf[jp][3], aB + bsw + jp*16*128);
      #pragma unroll
      for (int jp=0; jp<NBL; jp++){
        MMA8(acc[0][2*jp  ], af0[0],af0[1],af0[2],af0[3], bf[jp][0], bf[jp][2]);
        MMA8(acc[0][2*jp+1], af0[0],af0[1],af0[2],af0[3], bf[jp][1], bf[jp][3]);
        MMA8(acc[1][2*jp  ], af1[0],af1[1],af1[2],af1[3], bf[jp][0], bf[jp][2]);
        MMA8(acc[1][2*jp+1], af1[0],af1[1],af1[2],af1[3], bf[jp][1], bf[jp][3]);
      }
    }
    __syncthreads();
  }

  int r = lane >> 2, c2 = (lane & 3)*2;
  #pragma unroll
  for (int im=0; im<2; im++)
    #pragma unroll
    for (int jn=0; jn<NFR; jn++){
      int mr = m0 + wm*32 + im*16 + r;
      int nc = n0 + wn*NCOL + jn*8 + c2;
      epi(p, C, mr,   nc,   acc[im][jn][0]);
      epi(p, C, mr,   nc+1, acc[im][jn][1]);
      epi(p, C, mr+8, nc,   acc[im][jn][2]);
      epi(p, C, mr+8, nc+1, acc[im][jn][3]);
    }
}

/* ---------------- fp16 converters ---------------------------------------- */
__global__ void conv_wp16(const float* __restrict__ Wp){
  long i = (long)blockIdx.x*blockDim.x + threadIdx.x;   /* half2 index */
  const long tot = (long)VPAD*(H3/2);
  if (i >= tot) return;
  long row = i / (H3/2);
  long c2  = i % (H3/2);
  __half2* dst = (__half2*)g_wp16;
  if (row < VOC){
    const float2 v = *(const float2*)(Wp + row*H3 + c2*2);
    dst[i] = __floats2half2_rn(v.x, v.y);
  } else {
    dst[i] = __floats2half2_rn(0.f, 0.f);
  }
}
__global__ void conv_cat16(){
  long i = (long)blockIdx.x*blockDim.x + threadIdx.x;   /* half2 index */
  if (i >= (long)TB*(H3/2)) return;
  const float2 v = *(const float2*)(g_cat + i*2);
  ((__half2*)g_cat16)[i] = __floats2half2_rn(v.x, v.y);
}

/* ====== fp16 Wp GEMM: 128x256 CTA, 512 thr, 32x64 warp tile, K-iter=64 === */
#define WBM 128
#define WBN 256
#define WKI 64                          /* halfs per k-iteration             */
#define WABY (WBM*128)                  /* 16384 (128 rows x 128B)           */
#define WSBY (WABY + WBN*128)           /* 49152 per stage                   */
#define WSMEM (3*WSBY)                  /* 147456                            */

__global__ __launch_bounds__(512,1) void gemm_wp16(
    const __half* __restrict__ A, const __half* __restrict__ B,
    const float* __restrict__ bias, float* __restrict__ out)
{
  extern __shared__ float smf[];
  uint32_t sbase = (uint32_t)__cvta_generic_to_shared(smf);
  int tid = threadIdx.x;
  int lane = tid & 31, warp = tid >> 5;
  int wm = warp & 3, wn = warp >> 2;     /* 4 x 4 warp grid, 32x64 tiles     */
  int m0 = blockIdx.x * WBM, n0 = blockIdx.y * WBN;

  float acc[2][8][4];
  #pragma unroll
  for (int i=0;i<2;i++)
    #pragma unroll
    for (int j=0;j<8;j++){ acc[i][j][0]=0.f; acc[i][j][1]=0.f; acc[i][j][2]=0.f; acc[i][j][3]=0.f; }

  const int ktiles = H3/WKI;             /* 24 */

  auto load = [&](int st, int k0){       /* k0 in halfs */
    uint32_t ab = sbase + st*WSBY;
    uint32_t bb = ab + WABY;
    #pragma unroll
    for (int i=0;i<6;i++){               /* (128+256)*8 / 512 granules       */
      int g = tid + i*512;
      int r = g >> 3, gc = g & 7;
      int kcol = k0 + gc*8;              /* granule = 8 halfs = 16B          */
      if (r < WBM){
        uint32_t soff = (uint32_t)(r*128 + ((gc ^ (r&7))<<4));
        cpa16u(ab + soff, A + (long)(m0 + r)*H3 + kcol, 16);
      } else {
        int rb = r - WBM;
        uint32_t soff = (uint32_t)(rb*128 + ((gc ^ (rb&7))<<4));
        cpa16u(bb + soff, B + (long)(n0 + rb)*H3 + kcol, 16);
      }
    }
  };

  load(0, 0); CPA_COMMIT();
  load(1, WKI); CPA_COMMIT();

  int mi1 = (lane >> 3) & 1;
  int kg2 = lane >> 4;
  int ri  = lane & 7;
  int marow = wm*32 + mi1*8 + ri;
  int nbrow = wn*64 + mi1*8 + ri;
  int maxor = (marow & 7);
  int nbxor = (nbrow & 7);

  for (int kt = 0; kt < ktiles; kt++){
    if (kt + 2 < ktiles) load((kt+2)%3, (kt+2)*WKI);
    CPA_COMMIT();
    CPA_WAIT2();
    __syncthreads();

    uint32_t ab = sbase + (kt%3)*WSBY;
    uint32_t aA = ab + marow*128;
    uint32_t aB = ab + WABY + nbrow*128;

    #pragma unroll
    for (int kk=0; kk<4; kk++){          /* each kk = k16 halfs              */
      uint32_t asw = (uint32_t)(((kk*2 + kg2) ^ maxor) << 4);
      uint32_t bsw = (uint32_t)(((kk*2 + kg2) ^ nbxor) << 4);
      unsigned af0[4], af1[4], bf[4][4];
      LDSM_X4(af0[0],af0[1],af0[2],af0[3], aA + asw);
      LDSM_X4(af1[0],af1[1],af1[2],af1[3], aA + asw + 16*128);
      #pragma unroll
      for (int jb=0; jb<4; jb++)
        LDSM_X4(bf[jb][0],bf[jb][1],bf[jb][2],bf[jb][3], aB + bsw + jb*16*128);
      #pragma unroll
      for (int jb=0; jb<4; jb++){
        MMA16(acc[0][2*jb  ], af0[0],af0[1],af0[2],af0[3], bf[jb][0], bf[jb][2]);
        MMA16(acc[0][2*jb+1], af0[0],af0[1],af0[2],af0[3], bf[jb][1], bf[jb][3]);
        MMA16(acc[1][2*jb  ], af1[0],af1[1],af1[2],af1[3], bf[jb][0], bf[jb][2]);
        MMA16(acc[1][2*jb+1], af1[0],af1[1],af1[2],af1[3], bf[jb][1], bf[jb][3]);
      }
    }
    __syncthreads();
  }

  int r2 = lane >> 2, c2 = (lane & 3)*2;
  #pragma unroll
  for (int im=0; im<2; im++)
    #pragma unroll
    for (int nj=0; nj<8; nj++){
      int mr = m0 + wm*32 + im*16 + r2;
      int nc = n0 + wn*64 + nj*8 + c2;
      if (nc < VOC){
        float b0 = bias[nc], b1 = bias[nc+1];
        float* o0 = out + (long)mr*VE + nc;
        float* o1 = out + (long)(mr+8)*VE + nc;
        o0[0] = acc[im][nj][0] + b0;  o0[1] = acc[im][nj][1] + b1;
        o1[0] = acc[im][nj][2] + b0;  o1[1] = acc[im][nj][3] + b1;
      }
    }
}

/* ---------------- cat[:, 0:1024] = [h, y_emb] ---------------------------- */
__global__ void cat_copy(const float* __restrict__ h, const float* __restrict__ y){
  int i = blockIdx.x*blockDim.x + threadIdx.x;
  if (i >= TB*(HID/4)) return;
  int row = i / (HID/4);
  int c   = i % (HID/4);
  const float4* h4 = (const float4*)h;
  const float4* y4 = (const float4*)y;
  float4* cat4 = (float4*)g_cat;
  cat4[(long)row*(H3/4) + c]           = h4[i];
  cat4[(long)row*(H3/4) + (HID/4) + c] = y4[i];
}

/* ---------------- softmax over S; writes w (B,T,S) + dists (T,B,S) ------- */
__global__ void softmax_s(float* __restrict__ dists, const unsigned char* __restrict__ mask){
  int bt = blockIdx.x;                  /* b*T + t */
  int b = bt / T_LEN, t = bt % T_LEN;
  float* row = g_w + (long)bt*SEQ;
  const unsigned char* mrow = mask + (long)b*SEQ;
  int tid = threadIdx.x;                /* 128 */
  __shared__ float red[128];
  float mx = -1e30f;
  for (int s=tid; s<SEQ; s+=128){
    float x = mrow[s] ? -1e9f : row[s];
    mx = fmaxf(mx, x);
  }
  red[tid]=mx; __syncthreads();
  for (int off=64; off>0; off>>=1){ if (tid<off) red[tid]=fmaxf(red[tid],red[tid+off]); __syncthreads(); }
  mx = red[0]; __syncthreads();
  float sum=0.f;
  for (int s=tid; s<SEQ; s+=128){
    float x = mrow[s] ? -1e9f : row[s];
    sum += __expf(x-mx);
  }
  red[tid]=sum; __syncthreads();
  for (int off=64; off>0; off>>=1){ if (tid<off) red[tid]+=red[tid+off]; __syncthreads(); }
  float inv = 1.f/red[0];
  for (int s=tid; s<SEQ; s+=128){
    float x = mrow[s] ? -1e9f : row[s];
    float wv = __expf(x-mx)*inv;
    row[s] = wv;
    dists[((long)t*BATCH + b)*SEQ + s] = wv;
  }
}

/* -------- fused: gate + softmax over V + ext zero + pointer scatter ------ */
__global__ void softmax_v(float* __restrict__ out, const int* __restrict__ xids,
                          const float* __restrict__ vv, const float* __restrict__ bvv){
  int rid = blockIdx.x;                 /* t*B + b */
  int b = rid % BATCH, t = rid / BATCH;
  float* row = out + (long)rid*VE;
  int tid = threadIdx.x;                /* 512 */
  __shared__ float rm[512], rs[512];
  __shared__ float gsh;

  /* gate = sigmoid(cat[rid] . v + bv) */
  const float* cr = g_cat + (long)rid*H3;
  float s0 = 0.f;
  for (int j=tid; j<H3; j+=512) s0 += cr[j]*vv[j];
  rm[tid]=s0; __syncthreads();
  for (int off=256; off>0; off>>=1){ if (tid<off) rm[tid]+=rm[tid+off]; __syncthreads(); }
  if (tid==0) gsh = 1.f/(1.f+__expf(-(rm[0]+bvv[0])));
  __syncthreads();
  float g = gsh;

  /* online softmax over V */
  float m = row[tid], s = 1.f;
  for (int j=tid+512; j<VOC; j+=512){
    float x = row[j];
    if (x > m){ s = s*__expf(m-x) + 1.f; m = x; }
    else        s += __expf(x-m);
  }
  rm[tid]=m; rs[tid]=s; __syncthreads();
  for (int off=256; off>0; off>>=1){
    if (tid<off){
      float m2=rm[tid+off], s2=rs[tid+off];
      float M=fmaxf(rm[tid],m2);
      rs[tid]=rs[tid]*__expf(rm[tid]-M)+s2*__expf(m2-M);
      rm[tid]=M;
    }
    __syncthreads();
  }
  float M = rm[0];
  float gscale = g/rs[0];
  for (int j=tid; j<VOC; j+=512) row[j] = __expf(row[j]-M)*gscale;
  for (int j=VOC+tid; j<VE; j+=512) row[j] = 0.f;

  /* order the stores before cross-thread atomics on the same row */
  __threadfence(); __syncthreads();

  float omg = 1.f - g;
  for (int si=tid; si<SEQ; si+=512){
    float wv = g_w[((long)b*T_LEN + t)*SEQ + si];
    int col = xids[(long)si*BATCH + b];
    atomicAdd(row + col, omg*wv);
  }
}

/* ------------------------------- host ----------------------------------- */
template<int BMT, int DUAL>
static inline void launch_gemm(const GP& p, int batches){
  constexpr int SM = 3*((BMT+BN)*BK*4);
  static bool done = false;
  if (!done){
    cudaFuncSetAttribute(gemm_tf32<BMT,DUAL>,
                         cudaFuncAttributeMaxDynamicSharedMemorySize, SM);
    done = true;
  }
  dim3 grid((p.M+BMT-1)/BMT, (p.N+BN-1)/BN, batches);
  gemm_tf32<BMT,DUAL><<<grid, 256, SM>>>(p);
}

extern "C" void kernel_launch(void* const* d_in, const int* in_sizes, int n_in,
                              void* d_out, int out_size){
  const float* h    = (const float*)d_in[0];
  const float* yemb = (const float*)d_in[1];
  const float* mem  = (const float*)d_in[2];
  const unsigned char* mask = (const unsigned char*)d_in[3];
  const int* xids   = (const int*)d_in[4];
  int wb = 5;
  if (n_in >= 18 && in_sizes[5] == 1) wb = 6;   /* max_ext_len scalar present */
  const float* Wq = (const float*)d_in[wb+0];
  const float* bq = (const float*)d_in[wb+1];
  const float* Wk = (const float*)d_in[wb+2];
  const float* bk = (const float*)d_in[wb+3];
  const float* Wv = (const float*)d_in[wb+4];
  const float* bva= (const float*)d_in[wb+5];
  const float* Wo = (const float*)d_in[wb+6];
  const float* bo = (const float*)d_in[wb+7];
  const float* Wp = (const float*)d_in[wb+8];
  const float* bp = (const float*)d_in[wb+9];
  const float* vv = (const float*)d_in[wb+10];
  const float* bv = (const float*)d_in[wb+11];

  float* out   = (float*)d_out;
  float* dists = out + (long)TB*VE;

  cudaFuncSetAttribute(gemm_wp16, cudaFuncAttributeMaxDynamicSharedMemorySize, WSMEM);

  void *qB, *kB, *valT, *wbuf, *attsB, *catp, *wp16p, *cat16p;
  cudaGetSymbolAddress(&qB,   g_qB);
  cudaGetSymbolAddress(&kB,   g_kB);
  cudaGetSymbolAddress(&valT, g_valT);
  cudaGetSymbolAddress(&wbuf, g_w);
  cudaGetSymbolAddress(&attsB,g_atts);
  cudaGetSymbolAddress(&catp, g_cat);
  cudaGetSymbolAddress(&wp16p, g_wp16);
  cudaGetSymbolAddress(&cat16p, g_cat16);

  float scale = 1.0f/sqrtf((float)HID);

  /* Wp -> fp16 (independent of everything else; launch first) */
  {
    long tot = (long)VPAD*(H3/2);
    conv_wp16<<<(int)((tot + 255)/256), 256>>>(Wp);
  }

  /* cat[:,0:1024] = [h, y_emb] */
  cat_copy<<<(TB*(HID/4)+255)/256, 256>>>(h, yemb);

  GP p;

  /* q = (h@Wq^T + bq)*scale -> (B,T,H) */
  p = GP{};
  p.A = h; p.B = Wq; p.C = (float*)qB;
  p.lda = HID; p.ldb = HID; p.ldc = HID;
  p.M = TB; p.N = HID; p.K = HID;
  p.bias = bq; p.alpha = scale;
  p.mode = 1; p.D1 = BATCH; p.D2 = T_LEN;
  launch_gemm<64,0>(p, 1);

  /* fused k & val projection: B rows [0,512)=Wk, [512,1024)=Wv */
  p = GP{};
  p.A = mem; p.B = Wk; p.B2 = Wv;
  p.C = (float*)kB; p.C2 = (float*)valT;
  p.lda = HID; p.ldb = HID;
  p.M = SEQ*BATCH; p.N = 2*HID; p.K = HID;
  p.bias = bk; p.bias2 = bva; p.alpha = 1.f;
  p.mode = 3;
  launch_gemm<128,1>(p, 1);

  /* scores[b]: (T,S) = q_b @ k_b^T */
  p = GP{};
  p.A = (const float*)qB; p.B = (const float*)kB; p.C = (float*)wbuf;
  p.lda = HID; p.ldb = HID; p.ldc = SEQ;
  p.sA = (long)T_LEN*HID; p.sB = (long)SEQ*HID; p.sC = (long)T_LEN*SEQ;
  p.M = T_LEN; p.N = SEQ; p.K = HID;
  p.alpha = 1.f; p.mode = 0;
  launch_gemm<64,0>(p, BATCH);

  softmax_s<<<BATCH*T_LEN, 128>>>(dists, mask);

  /* atts[b]: (T,H) = w_b @ valT_b^T */
  p = GP{};
  p.A = (const float*)wbuf; p.B = (const float*)valT; p.C = (float*)attsB;
  p.lda = SEQ; p.ldb = SEQ; p.ldc = HID;
  p.sA = (long)T_LEN*SEQ; p.sB = (long)HID*SEQ; p.sC = (long)T_LEN*HID;
  p.M = T_LEN; p.N = HID; p.K = SEQ;
  p.alpha = 1.f; p.mode = 0;
  launch_gemm<64,0>(p, BATCH);

  /* cat[:,1024:1536] = atts@Wo^T + bo  (rows b*T+t -> t*B+b) */
  p = GP{};
  p.A = (const float*)attsB; p.B = Wo; p.C = (float*)catp;
  p.lda = HID; p.ldb = HID; p.ldc = H3;
  p.M = TB; p.N = HID; p.K = HID;
  p.bias = bo; p.alpha = 1.f;
  p.mode = 1; p.D1 = T_LEN; p.D2 = BATCH; p.col_off = 1024;
  launch_gemm<64,0>(p, 1);

  /* cat -> fp16 (after cat fully written) */
  {
    long tot = (long)TB*(H3/2);
    conv_cat16<<<(int)((tot + 255)/256), 256>>>();
  }

  /* logits = cat16@Wp16^T + bp -> d_out rows (fp16 MMA) */
  gemm_wp16<<<dim3(TB/WBM, VPAD/WBN), 512, WSMEM>>>(
      (const __half*)cat16p, (const __half*)wp16p, bp, out);

  /* fused gate + softmax over V + ext zero + scatter */
  softmax_v<<<TB, 512>>>(out, xids, vv, bv);

  (void)out_size; (void)n_in;
}